// round 6
// baseline (speedup 1.0000x reference)
#include <cuda_runtime.h>
#include <cstdint>
#include <math.h>

#define SEQ  2048
#define DM   1024
#define NH   16
#define HD   64
#define DFF  4096

// ---------------- scratch (no allocation allowed) ----------------
__device__ float g_normed [SEQ * DM];
__device__ float g_qkv    [SEQ * 3 * DM];
__device__ float g_q      [NH * SEQ * HD];
__device__ float g_k      [NH * SEQ * HD];
__device__ float g_v      [NH * SEQ * HD];
__device__ float g_attn   [SEQ * DM];
__device__ float g_x2     [SEQ * DM];
__device__ float g_normed2[SEQ * DM];
__device__ float g_ffh    [SEQ * DFF];
// tf32-pre-rounded weight copies
__device__ float g_wqkv_t [DM * 3 * DM];
__device__ float g_wout_t [DM * DM];
__device__ float g_wff1_t [DM * DFF];
__device__ float g_wff2_t [DFF * DM];

// ---------------- tf32 helpers ----------------
__device__ __forceinline__ float tf32r(float x) {
    float y;
    asm("cvt.rna.tf32.f32 %0, %1;" : "=f"(y) : "f"(x));
    return y;
}
__device__ __forceinline__ float4 cvt4(float4 v) {
    v.x = tf32r(v.x); v.y = tf32r(v.y); v.z = tf32r(v.z); v.w = tf32r(v.w);
    return v;
}
__device__ __forceinline__ void mma8(float* d, const float* a, const float* b) {
    asm volatile(
        "mma.sync.aligned.m16n8k8.row.col.f32.tf32.tf32.f32 "
        "{%0,%1,%2,%3}, {%4,%5,%6,%7}, {%8,%9}, {%0,%1,%2,%3};\n"
        : "+f"(d[0]), "+f"(d[1]), "+f"(d[2]), "+f"(d[3])
        : "r"(__float_as_uint(a[0])), "r"(__float_as_uint(a[1])),
          "r"(__float_as_uint(a[2])), "r"(__float_as_uint(a[3])),
          "r"(__float_as_uint(b[0])), "r"(__float_as_uint(b[1])));
}
__device__ __forceinline__ void cp16(void* sdst, const void* gsrc) {
    unsigned int d = (unsigned int)__cvta_generic_to_shared(sdst);
    asm volatile("cp.async.cg.shared.global [%0], [%1], 16;\n" :: "r"(d), "l"(gsrc));
}
// ldmatrix x4 on tf32 bits: returns the 4 regs of an m16n8k8 tf32 A-fragment
__device__ __forceinline__ void ldsm4(float* a, const void* saddr) {
    unsigned int ad = (unsigned int)__cvta_generic_to_shared(saddr);
    asm volatile("ldmatrix.sync.aligned.m8n8.x4.shared.b16 {%0,%1,%2,%3}, [%4];\n"
        : "=r"(*(unsigned int*)&a[0]), "=r"(*(unsigned int*)&a[1]),
          "=r"(*(unsigned int*)&a[2]), "=r"(*(unsigned int*)&a[3])
        : "r"(ad));
}

// ---------------- fused weight pre-round kernel (all 4 weights) ----------------
__global__ __launch_bounds__(256) void round_all_kernel(
    const float* __restrict__ s0, float* __restrict__ d0, int n0,
    const float* __restrict__ s1, float* __restrict__ d1, int n1,
    const float* __restrict__ s2, float* __restrict__ d2, int n2,
    const float* __restrict__ s3, float* __restrict__ d3, int n3)
{
    int i = blockIdx.x * blockDim.x + threadIdx.x;
    int stride = gridDim.x * blockDim.x;
    for (int j = i; j < n0; j += stride)
        reinterpret_cast<float4*>(d0)[j] = cvt4(reinterpret_cast<const float4*>(s0)[j]);
    for (int j = i; j < n1; j += stride)
        reinterpret_cast<float4*>(d1)[j] = cvt4(reinterpret_cast<const float4*>(s1)[j]);
    for (int j = i; j < n2; j += stride)
        reinterpret_cast<float4*>(d2)[j] = cvt4(reinterpret_cast<const float4*>(s2)[j]);
    for (int j = i; j < n3; j += stride)
        reinterpret_cast<float4*>(d3)[j] = cvt4(reinterpret_cast<const float4*>(s3)[j]);
}

// ---------------- LayerNorm (tf32-rounded output) ----------------
__global__ __launch_bounds__(256) void ln_kernel(
    const float* __restrict__ x, const float* __restrict__ g,
    const float* __restrict__ b, float* __restrict__ out)
{
    int row = blockIdx.x;
    int tid = threadIdx.x;
    const float* xr = x + (size_t)row * DM;
    float4 xv = reinterpret_cast<const float4*>(xr)[tid];
    float s  = xv.x + xv.y + xv.z + xv.w;
    float sq = xv.x*xv.x + xv.y*xv.y + xv.z*xv.z + xv.w*xv.w;

    __shared__ float sh1[256], sh2[256];
    sh1[tid] = s; sh2[tid] = sq;
    __syncthreads();
    #pragma unroll
    for (int o = 128; o > 0; o >>= 1) {
        if (tid < o) { sh1[tid] += sh1[tid + o]; sh2[tid] += sh2[tid + o]; }
        __syncthreads();
    }
    float mu   = sh1[0] * (1.0f / DM);
    float var  = sh2[0] * (1.0f / DM) - mu * mu;
    float rstd = rsqrtf(var + 1e-5f);

    float4 gv = reinterpret_cast<const float4*>(g)[tid];
    float4 bv = reinterpret_cast<const float4*>(b)[tid];
    float4 o4;
    o4.x = tf32r((xv.x - mu) * rstd * gv.x + bv.x);
    o4.y = tf32r((xv.y - mu) * rstd * gv.y + bv.y);
    o4.z = tf32r((xv.z - mu) * rstd * gv.z + bv.z);
    o4.w = tf32r((xv.w - mu) * rstd * gv.w + bv.w);
    reinterpret_cast<float4*>(out + (size_t)row * DM)[tid] = o4;
}

// ---------------- tf32 MMA GEMM v3 ------------------------------------------
// Block tile 128 x TN (TN = 256 or 128), 256 threads = 8 warps, 64x64 or 32x64
// warp tiles, 3-stage cp.async, A-fragments via ldmatrix. Inputs pre-rounded.
// grid.x = M blocks (B-tile L2 locality), grid.y = N blocks.
#define ASTR 20
#define GNST 3

template<int TN, int OP>
__global__ __launch_bounds__(256) void mma_gemm3(
    const float* __restrict__ A, const float* __restrict__ B,
    const float* __restrict__ bias, const float* __restrict__ res,
    float* __restrict__ C, int M, int N, int K)
{
    constexpr int BSTR  = TN + 8;                  // 264 or 136 (≡8 mod 32)
    constexpr int NWN   = TN / 64;                 // n-warps: 4 or 2
    constexpr int MT    = (TN == 256) ? 4 : 2;     // m-tiles (16 rows) per warp
    constexpr int STAGE = 128 * ASTR + 16 * BSTR;  // floats per stage

    extern __shared__ float sm[];

    const int tid  = threadIdx.x;
    const int lane = tid & 31;
    const int warp = tid >> 5;
    const int g    = lane >> 2;
    const int tig  = lane & 3;
    const int wm   = warp / NWN;
    const int wn   = warp % NWN;
    const int m0   = blockIdx.x * 128;
    const int n0   = blockIdx.y * TN;

    // cp.async coords (256 threads)
    const int ar = tid >> 1;                  // A row 0..127
    const int ac = (tid & 1) * 8;             // A col 0 or 8 (2 cp16 each)
    const int br = tid >> 4;                  // B row 0..15
    const int bc = (tid & 15) * (TN / 16);    // B col chunk (TN/64 cp16 each)

    // ldmatrix per-lane address components
    const int lt = lane >> 3;                 // tile id 0..3
    const int li = lane & 7;                  // row within tile
    const int lrow_base = wm * (MT * 16) + (lt & 1) * 8 + li;
    const int lcol_base = (lt >> 1) * 4;

    float acc[MT][8][4];
    #pragma unroll
    for (int mt = 0; mt < MT; mt++)
        #pragma unroll
        for (int nt = 0; nt < 8; nt++)
            #pragma unroll
            for (int i = 0; i < 4; i++) acc[mt][nt][i] = 0.0f;

    const int nsteps = K >> 4;

    // prologue: stages 0..1
    #pragma unroll
    for (int s = 0; s < GNST - 1; s++) {
        float* As = sm + s * STAGE;
        float* Bs = As + 128 * ASTR;
        cp16(&As[ar * ASTR + ac],     A + (size_t)(m0 + ar) * K + s * 16 + ac);
        cp16(&As[ar * ASTR + ac + 4], A + (size_t)(m0 + ar) * K + s * 16 + ac + 4);
        #pragma unroll
        for (int i = 0; i < TN / 64; i++)
            cp16(&Bs[br * BSTR + bc + i * 4], B + (size_t)(s * 16 + br) * N + n0 + bc + i * 4);
        asm volatile("cp.async.commit_group;\n");
    }

    for (int it = 0; it < nsteps; it++) {
        asm volatile("cp.async.wait_group %0;\n" :: "n"(GNST - 2));
        __syncthreads();

        // prefetch stage it+2
        if (it + GNST - 1 < nsteps) {
            const int s  = (it + GNST - 1) % GNST;
            const int kt = (it + GNST - 1) * 16;
            float* As = sm + s * STAGE;
            float* Bs = As + 128 * ASTR;
            cp16(&As[ar * ASTR + ac],     A + (size_t)(m0 + ar) * K + kt + ac);
            cp16(&As[ar * ASTR + ac + 4], A + (size_t)(m0 + ar) * K + kt + ac + 4);
            #pragma unroll
            for (int i = 0; i < TN / 64; i++)
                cp16(&Bs[br * BSTR + bc + i * 4], B + (size_t)(kt + br) * N + n0 + bc + i * 4);
        }
        asm volatile("cp.async.commit_group;\n");

        const float* As = sm + (it % GNST) * STAGE;
        const float* Bs = As + 128 * ASTR;

        #pragma unroll
        for (int kb = 0; kb < 16; kb += 8) {
            float a[MT][4], b[8][2];
            #pragma unroll
            for (int mt = 0; mt < MT; mt++)
                ldsm4(a[mt], &As[(lrow_base + mt * 16) * ASTR + kb + lcol_base]);
            #pragma unroll
            for (int nt = 0; nt < 8; nt++) {
                const int c = wn * 64 + nt * 8 + g;
                b[nt][0] = Bs[(kb + tig)     * BSTR + c];
                b[nt][1] = Bs[(kb + tig + 4) * BSTR + c];
            }
            #pragma unroll
            for (int mt = 0; mt < MT; mt++)
                #pragma unroll
                for (int nt = 0; nt < 8; nt++)
                    mma8(acc[mt][nt], a[mt], b[nt]);
        }
    }

    // epilogue
    #pragma unroll
    for (int mt = 0; mt < MT; mt++) {
        const int r0 = m0 + wm * (MT * 16) + mt * 16 + g;
        const int r1 = r0 + 8;
        #pragma unroll
        for (int nt = 0; nt < 8; nt++) {
            const int c = n0 + wn * 64 + nt * 8 + tig * 2;
            const float b0 = bias[c], b1 = bias[c + 1];
            float v0 = acc[mt][nt][0] + b0;
            float v1 = acc[mt][nt][1] + b1;
            float v2 = acc[mt][nt][2] + b0;
            float v3 = acc[mt][nt][3] + b1;
            if (OP == 1) {
                const float2 ra = *reinterpret_cast<const float2*>(res + (size_t)r0 * N + c);
                const float2 rb = *reinterpret_cast<const float2*>(res + (size_t)r1 * N + c);
                v0 += ra.x; v1 += ra.y; v2 += rb.x; v3 += rb.y;
            }
            if (OP == 2) {
                v0 = tf32r(0.5f * v0 * (1.0f + erff(v0 * 0.70710678118654752f)));
                v1 = tf32r(0.5f * v1 * (1.0f + erff(v1 * 0.70710678118654752f)));
                v2 = tf32r(0.5f * v2 * (1.0f + erff(v2 * 0.70710678118654752f)));
                v3 = tf32r(0.5f * v3 * (1.0f + erff(v3 * 0.70710678118654752f)));
            }
            *reinterpret_cast<float2*>(C + (size_t)r0 * N + c) = make_float2(v0, v1);
            *reinterpret_cast<float2*>(C + (size_t)r1 * N + c) = make_float2(v2, v3);
        }
    }
}

// ---------------- split qkv, L2-normalize q,k; relayout to [H,L,64] --
__global__ __launch_bounds__(256) void qkvnorm_kernel(
    const float* __restrict__ qkv, float* __restrict__ Q,
    float* __restrict__ Km, float* __restrict__ V)
{
    int gw   = (blockIdx.x * blockDim.x + threadIdx.x) >> 5;
    int lane = threadIdx.x & 31;
    int l = gw >> 4;
    int h = gw & 15;

    const float* base = qkv + (size_t)l * (3 * DM);
    size_t oidx = ((size_t)h * SEQ + l) * HD + lane * 2;

    float2 qv = *reinterpret_cast<const float2*>(base + h * HD + lane * 2);
    float ssq = qv.x * qv.x + qv.y * qv.y;
    #pragma unroll
    for (int o = 16; o > 0; o >>= 1) ssq += __shfl_xor_sync(0xffffffffu, ssq, o);
    float scq = 0.125f / fmaxf(sqrtf(ssq), 1e-12f);
    *reinterpret_cast<float2*>(Q + oidx) = make_float2(qv.x * scq, qv.y * scq);

    float2 kv = *reinterpret_cast<const float2*>(base + DM + h * HD + lane * 2);
    float ssk = kv.x * kv.x + kv.y * kv.y;
    #pragma unroll
    for (int o = 16; o > 0; o >>= 1) ssk += __shfl_xor_sync(0xffffffffu, ssk, o);
    float sck = 1.0f / fmaxf(sqrtf(ssk), 1e-12f);
    *reinterpret_cast<float2*>(Km + oidx) = make_float2(kv.x * sck, kv.y * sck);

    float2 vv = *reinterpret_cast<const float2*>(base + 2 * DM + h * HD + lane * 2);
    *reinterpret_cast<float2*>(V + oidx) = vv;
}

// ---------------- MMA attention (tf32-rounded output) ----------------
#define APAD 68
__global__ __launch_bounds__(256) void attn_mma_kernel(
    const float* __restrict__ Q, const float* __restrict__ Km,
    const float* __restrict__ V, const float* __restrict__ lcc,
    float* __restrict__ out)
{
    __shared__ __align__(16) float pool[128 * APAD];
    __shared__ float lccs[64];
    float* Qs = pool;
    float* Ks = pool;
    float* Vs = pool + 64 * APAD;

    const int h    = blockIdx.y;
    const int m0   = blockIdx.x * 128;
    const int tid  = threadIdx.x;
    const int lane = tid & 31;
    const int warp = tid >> 5;
    const int g    = lane >> 2;
    const int tig  = lane & 3;

    {
        const float* Qg = Q + ((size_t)h * SEQ + m0) * HD;
        #pragma unroll
        for (int t = 0; t < 8; t++) {
            int idx = t * 256 + tid;
            int row = idx >> 4;
            int c4  = (idx & 15) * 4;
            float4 v = *reinterpret_cast<const float4*>(Qg + (size_t)row * HD + c4);
            *reinterpret_cast<float4*>(&Qs[row * APAD + c4]) = cvt4(v);
        }
    }
    __syncthreads();

    float qa[8][4];
    {
        const int r = warp * 16;
        #pragma unroll
        for (int kc = 0; kc < 8; kc++) {
            qa[kc][0] = Qs[(r + g)     * APAD + kc * 8 + tig];
            qa[kc][1] = Qs[(r + 8 + g) * APAD + kc * 8 + tig];
            qa[kc][2] = Qs[(r + g)     * APAD + kc * 8 + tig + 4];
            qa[kc][3] = Qs[(r + 8 + g) * APAD + kc * 8 + tig + 4];
        }
    }

    const float rb0 = lcc[m0 + warp * 16 + g]     * 0.05f;
    const float rb1 = lcc[m0 + warp * 16 + 8 + g] * 0.05f;

    float o[8][4];
    #pragma unroll
    for (int nt = 0; nt < 8; nt++)
        #pragma unroll
        for (int i = 0; i < 4; i++) o[nt][i] = 0.0f;
    float d0 = 0.0f, d1 = 0.0f;

    const int src0 = (g << 2) | (tig >> 1);
    const int src1 = src0 + 2;
    const bool odd = (tig & 1);

    for (int kt = 0; kt < SEQ; kt += 64) {
        __syncthreads();
        {
            const float* Kg = Km + ((size_t)h * SEQ + kt) * HD;
            const float* Vg = V  + ((size_t)h * SEQ + kt) * HD;
            int row = tid >> 4;
            int c4  = (tid & 15) * 4;
            #pragma unroll
            for (int t = 0; t < 4; t++) {
                int r = row + t * 16;
                float4 kv = *reinterpret_cast<const float4*>(Kg + (size_t)r * HD + c4);
                float4 vv = *reinterpret_cast<const float4*>(Vg + (size_t)r * HD + c4);
                *reinterpret_cast<float4*>(&Ks[r * APAD + c4]) = cvt4(kv);
                *reinterpret_cast<float4*>(&Vs[r * APAD + c4]) = cvt4(vv);
            }
            if (tid < 64) lccs[tid] = lcc[kt + tid] * 0.05f;
        }
        __syncthreads();

        float s[8][4];
        #pragma unroll
        for (int nt = 0; nt < 8; nt++)
            #pragma unroll
            for (int i = 0; i < 4; i++) s[nt][i] = 0.0f;

        #pragma unroll
        for (int kc = 0; kc < 8; kc++) {
            #pragma unroll
            for (int nt = 0; nt < 8; nt++) {
                float b[2];
                b[0] = Ks[(nt * 8 + g) * APAD + kc * 8 + tig];
                b[1] = Ks[(nt * 8 + g) * APAD + kc * 8 + tig + 4];
                mma8(s[nt], qa[kc], b);
            }
        }

        #pragma unroll
        for (int nt = 0; nt < 8; nt++) {
            float cb0 = lccs[nt * 8 + tig * 2];
            float cb1 = lccs[nt * 8 + tig * 2 + 1];
            float v0 = s[nt][0] + rb0 + cb0;
            float v1 = s[nt][1] + rb0 + cb1;
            float v2 = s[nt][2] + rb1 + cb0;
            float v3 = s[nt][3] + rb1 + cb1;
            v0 = fminf(10.0f, fmaxf(-10.0f, v0));
            v1 = fminf(10.0f, fmaxf(-10.0f, v1));
            v2 = fminf(10.0f, fmaxf(-10.0f, v2));
            v3 = fminf(10.0f, fmaxf(-10.0f, v3));
            float p0 = tf32r(__expf(v0));
            float p1 = tf32r(__expf(v1));
            float p2 = tf32r(__expf(v2));
            float p3 = tf32r(__expf(v3));
            s[nt][0] = p0; s[nt][1] = p1; s[nt][2] = p2; s[nt][3] = p3;
            d0 += p0 + p1;
            d1 += p2 + p3;
        }

        #pragma unroll
        for (int kc = 0; kc < 8; kc++) {
            float t00 = __shfl_sync(0xffffffffu, s[kc][0], src0);
            float t01 = __shfl_sync(0xffffffffu, s[kc][1], src0);
            float t02 = __shfl_sync(0xffffffffu, s[kc][2], src0);
            float t03 = __shfl_sync(0xffffffffu, s[kc][3], src0);
            float t10 = __shfl_sync(0xffffffffu, s[kc][0], src1);
            float t11 = __shfl_sync(0xffffffffu, s[kc][1], src1);
            float t12 = __shfl_sync(0xffffffffu, s[kc][2], src1);
            float t13 = __shfl_sync(0xffffffffu, s[kc][3], src1);
            float a[4];
            a[0] = odd ? t01 : t00;
            a[1] = odd ? t03 : t02;
            a[2] = odd ? t11 : t10;
            a[3] = odd ? t13 : t12;
            #pragma unroll
            for (int nt = 0; nt < 8; nt++) {
                float b[2];
                b[0] = Vs[(kc * 8 + tig)     * APAD + nt * 8 + g];
                b[1] = Vs[(kc * 8 + tig + 4) * APAD + nt * 8 + g];
                mma8(o[nt], a, b);
            }
        }
    }

    d0 += __shfl_xor_sync(0xffffffffu, d0, 1);
    d0 += __shfl_xor_sync(0xffffffffu, d0, 2);
    d1 += __shfl_xor_sync(0xffffffffu, d1, 1);
    d1 += __shfl_xor_sync(0xffffffffu, d1, 2);
    const float inv0 = 1.0f / d0;
    const float inv1 = 1.0f / d1;

    const int r0 = m0 + warp * 16 + g;
    const int r1 = r0 + 8;
    #pragma unroll
    for (int nt = 0; nt < 8; nt++) {
        const int c = h * HD + nt * 8 + tig * 2;
        *reinterpret_cast<float2*>(out + (size_t)r0 * DM + c) =
            make_float2(tf32r(o[nt][0] * inv0), tf32r(o[nt][1] * inv0));
        *reinterpret_cast<float2*>(out + (size_t)r1 * DM + c) =
            make_float2(tf32r(o[nt][2] * inv1), tf32r(o[nt][3] * inv1));
    }
}

// ---------------- launch --------------------------------------------------------
extern "C" void kernel_launch(void* const* d_in, const int* in_sizes, int n_in,
                              void* d_out, int out_size)
{
    const float* x     = (const float*)d_in[0];
    const float* lcc   = (const float*)d_in[1];
    const float* w_qkv = (const float*)d_in[2];
    const float* b_qkv = (const float*)d_in[3];
    const float* w_out = (const float*)d_in[4];
    const float* b_out = (const float*)d_in[5];
    const float* ln1_g = (const float*)d_in[6];
    const float* ln1_b = (const float*)d_in[7];
    const float* ln2_g = (const float*)d_in[8];
    const float* ln2_b = (const float*)d_in[9];
    const float* w_ff1 = (const float*)d_in[10];
    const float* b_ff1 = (const float*)d_in[11];
    const float* w_ff2 = (const float*)d_in[12];
    const float* b_ff2 = (const float*)d_in[13];
    float* out = (float*)d_out;

    float *normed, *qkv, *q, *k, *v, *attn, *x2, *normed2, *ffh;
    float *wqkv_t, *wout_t, *wff1_t, *wff2_t;
    cudaGetSymbolAddress((void**)&normed,  g_normed);
    cudaGetSymbolAddress((void**)&qkv,     g_qkv);
    cudaGetSymbolAddress((void**)&q,       g_q);
    cudaGetSymbolAddress((void**)&k,       g_k);
    cudaGetSymbolAddress((void**)&v,       g_v);
    cudaGetSymbolAddress((void**)&attn,    g_attn);
    cudaGetSymbolAddress((void**)&x2,      g_x2);
    cudaGetSymbolAddress((void**)&normed2, g_normed2);
    cudaGetSymbolAddress((void**)&ffh,     g_ffh);
    cudaGetSymbolAddress((void**)&wqkv_t,  g_wqkv_t);
    cudaGetSymbolAddress((void**)&wout_t,  g_wout_t);
    cudaGetSymbolAddress((void**)&wff1_t,  g_wff1_t);
    cudaGetSymbolAddress((void**)&wff2_t,  g_wff2_t);

    const int smem256 = GNST * (128 * ASTR + 16 * 264) * 4;
    const int smem128 = GNST * (128 * ASTR + 16 * 136) * 4;
    cudaFuncSetAttribute(mma_gemm3<256,0>, cudaFuncAttributeMaxDynamicSharedMemorySize, smem256);
    cudaFuncSetAttribute(mma_gemm3<256,2>, cudaFuncAttributeMaxDynamicSharedMemorySize, smem256);
    cudaFuncSetAttribute(mma_gemm3<128,1>, cudaFuncAttributeMaxDynamicSharedMemorySize, smem128);

    // 0. pre-round all weights to tf32 (single launch)
    round_all_kernel<<<296, 256>>>(
        w_qkv, wqkv_t, DM * 3 * DM / 4,
        w_out, wout_t, DM * DM / 4,
        w_ff1, wff1_t, DM * DFF / 4,
        w_ff2, wff2_t, DFF * DM / 4);

    // 1. LN1
    ln_kernel<<<SEQ, 256>>>(x, ln1_g, ln1_b, normed);
    // 2. QKV projection [2048,1024]@[1024,3072], 128x256 tiles
    mma_gemm3<256,0><<<dim3(SEQ / 128, 3 * DM / 256), 256, smem256>>>(
        normed, wqkv_t, b_qkv, nullptr, qkv, SEQ, 3 * DM, DM);
    // 3. split + cosine-normalize + relayout
    qkvnorm_kernel<<<(SEQ * NH * 32) / 256, 256>>>(qkv, q, k, v);
    // 4. attention
    attn_mma_kernel<<<dim3(SEQ / 128, NH), 256>>>(q, k, v, lcc, attn);
    // 5. out projection + residual, 128x128 tiles
    mma_gemm3<128,1><<<dim3(SEQ / 128, DM / 128), 256, smem128>>>(
        attn, wout_t, b_out, x, x2, SEQ, DM, DM);
    // 6. LN2
    ln_kernel<<<SEQ, 256>>>(x2, ln2_g, ln2_b, normed2);
    // 7. FF1 + exact GELU, 128x256 tiles
    mma_gemm3<256,2><<<dim3(SEQ / 128, DFF / 256), 256, smem256>>>(
        normed2, wff1_t, b_ff1, nullptr, ffh, SEQ, DFF, DM);
    // 8. FF2 + residual -> out, 128x128 tiles
    mma_gemm3<128,1><<<dim3(SEQ / 128, DM / 128), 256, smem128>>>(
        ffh, wff2_t, b_ff2, x2, out, SEQ, DM, DFF);
}

// round 7
// speedup vs baseline: 2.1654x; 2.1654x over previous
#include <cuda_runtime.h>
#include <cuda_fp16.h>
#include <cstdint>
#include <math.h>

#define SEQ  2048
#define DM   1024
#define NH   16
#define HD   64
#define DFF  4096

// ---------------- scratch (no allocation allowed) ----------------
__device__ __half g_normed [SEQ * DM];
__device__ __half g_qkv    [SEQ * 3 * DM];
__device__ __half g_q      [NH * SEQ * HD];
__device__ __half g_k      [NH * SEQ * HD];
__device__ __half g_v      [NH * SEQ * HD];
__device__ __half g_attn   [SEQ * DM];
__device__ float  g_x2     [SEQ * DM];
__device__ __half g_normed2[SEQ * DM];
__device__ __half g_ffh    [SEQ * DFF];
// fp16 weight copies
__device__ __half g_wqkv_h [DM * 3 * DM];
__device__ __half g_wout_h [DM * DM];
__device__ __half g_wff1_h [DM * DFF];
__device__ __half g_wff2_h [DFF * DM];

// ---------------- helpers ----------------
__device__ __forceinline__ unsigned h2u(__half2 h) { return *reinterpret_cast<unsigned*>(&h); }

__device__ __forceinline__ void mma16(float* d, const unsigned* a, const unsigned* b) {
    asm volatile(
        "mma.sync.aligned.m16n8k16.row.col.f32.f16.f16.f32 "
        "{%0,%1,%2,%3}, {%4,%5,%6,%7}, {%8,%9}, {%0,%1,%2,%3};\n"
        : "+f"(d[0]), "+f"(d[1]), "+f"(d[2]), "+f"(d[3])
        : "r"(a[0]), "r"(a[1]), "r"(a[2]), "r"(a[3]), "r"(b[0]), "r"(b[1]));
}
__device__ __forceinline__ void cp16(void* sdst, const void* gsrc) {
    unsigned int d = (unsigned int)__cvta_generic_to_shared(sdst);
    asm volatile("cp.async.cg.shared.global [%0], [%1], 16;\n" :: "r"(d), "l"(gsrc));
}
__device__ __forceinline__ void ldsm4(unsigned* r, const void* saddr) {
    unsigned int ad = (unsigned int)__cvta_generic_to_shared(saddr);
    asm volatile("ldmatrix.sync.aligned.m8n8.x4.shared.b16 {%0,%1,%2,%3}, [%4];\n"
        : "=r"(r[0]), "=r"(r[1]), "=r"(r[2]), "=r"(r[3]) : "r"(ad));
}
__device__ __forceinline__ void ldsm4t(unsigned* r, const void* saddr) {
    unsigned int ad = (unsigned int)__cvta_generic_to_shared(saddr);
    asm volatile("ldmatrix.sync.aligned.m8n8.x4.trans.shared.b16 {%0,%1,%2,%3}, [%4];\n"
        : "=r"(r[0]), "=r"(r[1]), "=r"(r[2]), "=r"(r[3]) : "r"(ad));
}

// ---------------- fused weight fp32 -> fp16 convert ----------------
__global__ __launch_bounds__(256) void cvt_all_kernel(
    const float* __restrict__ s0, __half* __restrict__ d0, int n0,
    const float* __restrict__ s1, __half* __restrict__ d1, int n1,
    const float* __restrict__ s2, __half* __restrict__ d2, int n2,
    const float* __restrict__ s3, __half* __restrict__ d3, int n3)
{
    int i = blockIdx.x * blockDim.x + threadIdx.x;
    int stride = gridDim.x * blockDim.x;
    #define CVT_LOOP(S, D, N) \
    for (int j = i; j < N; j += stride) { \
        float4 v = reinterpret_cast<const float4*>(S)[j]; \
        __half2 lo = __floats2half2_rn(v.x, v.y); \
        __half2 hi = __floats2half2_rn(v.z, v.w); \
        reinterpret_cast<uint2*>(D)[j] = make_uint2(h2u(lo), h2u(hi)); \
    }
    CVT_LOOP(s0, d0, n0) CVT_LOOP(s1, d1, n1) CVT_LOOP(s2, d2, n2) CVT_LOOP(s3, d3, n3)
    #undef CVT_LOOP
}

// ---------------- LayerNorm (fp16 output: feeds GEMM A) ----------------
__global__ __launch_bounds__(256) void ln_kernel(
    const float* __restrict__ x, const float* __restrict__ g,
    const float* __restrict__ b, __half* __restrict__ out)
{
    int row = blockIdx.x;
    int tid = threadIdx.x;
    const float* xr = x + (size_t)row * DM;
    float4 xv = reinterpret_cast<const float4*>(xr)[tid];
    float s  = xv.x + xv.y + xv.z + xv.w;
    float sq = xv.x*xv.x + xv.y*xv.y + xv.z*xv.z + xv.w*xv.w;

    __shared__ float sh1[256], sh2[256];
    sh1[tid] = s; sh2[tid] = sq;
    __syncthreads();
    #pragma unroll
    for (int o = 128; o > 0; o >>= 1) {
        if (tid < o) { sh1[tid] += sh1[tid + o]; sh2[tid] += sh2[tid + o]; }
        __syncthreads();
    }
    float mu   = sh1[0] * (1.0f / DM);
    float var  = sh2[0] * (1.0f / DM) - mu * mu;
    float rstd = rsqrtf(var + 1e-5f);

    float4 gv = reinterpret_cast<const float4*>(g)[tid];
    float4 bv = reinterpret_cast<const float4*>(b)[tid];
    __half2 lo = __floats2half2_rn((xv.x - mu) * rstd * gv.x + bv.x,
                                   (xv.y - mu) * rstd * gv.y + bv.y);
    __half2 hi = __floats2half2_rn((xv.z - mu) * rstd * gv.z + bv.z,
                                   (xv.w - mu) * rstd * gv.w + bv.w);
    reinterpret_cast<uint2*>(out + (size_t)row * DM)[tid] = make_uint2(h2u(lo), h2u(hi));
}

// ---------------- fp16 MMA GEMM: 128x128 block, 8 warps (4x2), BK=32 ---------
// 3-stage cp.async; A frags via ldmatrix.x4; B frags via ldmatrix.x4.trans.
// OP = 0: half C = A*B + bias
// OP = 1: float C = A*B + bias + res (fp32 residual)
// OP = 2: half C = gelu(A*B + bias)
#define ASTR 40     // halves (80B rows; ldmatrix banks 20k%32 all distinct)
#define BSTR 136    // halves (272B rows = 68 words === 4 mod 32)
#define HBK  32
#define STAGE_H (128 * ASTR + HBK * BSTR)
#define GNST 3

template<int OP>
__global__ __launch_bounds__(256) void hgemm(
    const __half* __restrict__ A, const __half* __restrict__ B,
    const float* __restrict__ bias, const float* __restrict__ res,
    void* __restrict__ Cv, int M, int N, int K)
{
    extern __shared__ __half sh[];

    const int tid  = threadIdx.x;
    const int lane = tid & 31;
    const int warp = tid >> 5;
    const int g    = lane >> 2;
    const int tig  = lane & 3;
    const int wm   = warp >> 1;       // 0..3
    const int wn   = warp & 1;        // 0..1
    const int m0   = blockIdx.x * 128;
    const int n0   = blockIdx.y * 128;

    const int lt = lane >> 3;         // ldmatrix tile id
    const int li = lane & 7;
    const int arow_l = wm * 32 + (lt & 1) * 8 + li;   // + mt*16
    const int acol_l = (lt >> 1) * 8;                 // + kb
    const int brow_l = (lt & 1) * 8 + li;             // + kb
    const int bcol_l = wn * 64 + (lt >> 1) * 8;       // + ntp*16

    float acc[2][8][4];
    #pragma unroll
    for (int mt = 0; mt < 2; mt++)
        #pragma unroll
        for (int nt = 0; nt < 8; nt++)
            #pragma unroll
            for (int i = 0; i < 4; i++) acc[mt][nt][i] = 0.0f;

    const int nsteps = K >> 5;

    // prologue
    #pragma unroll
    for (int s = 0; s < GNST - 1; s++) {
        __half* As = sh + s * STAGE_H;
        __half* Bs = As + 128 * ASTR;
        #pragma unroll
        for (int t = 0; t < 2; t++) {
            int idx = t * 256 + tid;
            int arw = idx >> 2, aof = (idx & 3) * 8;
            cp16(&As[arw * ASTR + aof], A + (size_t)(m0 + arw) * K + s * HBK + aof);
            int brw = idx >> 4, bof = (idx & 15) * 8;
            cp16(&Bs[brw * BSTR + bof], B + (size_t)(s * HBK + brw) * N + n0 + bof);
        }
        asm volatile("cp.async.commit_group;\n");
    }

    for (int it = 0; it < nsteps; it++) {
        asm volatile("cp.async.wait_group %0;\n" :: "n"(GNST - 2));
        __syncthreads();

        if (it + GNST - 1 < nsteps) {
            const int s  = (it + GNST - 1) % GNST;
            const int kt = (it + GNST - 1) * HBK;
            __half* As = sh + s * STAGE_H;
            __half* Bs = As + 128 * ASTR;
            #pragma unroll
            for (int t = 0; t < 2; t++) {
                int idx = t * 256 + tid;
                int arw = idx >> 2, aof = (idx & 3) * 8;
                cp16(&As[arw * ASTR + aof], A + (size_t)(m0 + arw) * K + kt + aof);
                int brw = idx >> 4, bof = (idx & 15) * 8;
                cp16(&Bs[brw * BSTR + bof], B + (size_t)(kt + brw) * N + n0 + bof);
            }
        }
        asm volatile("cp.async.commit_group;\n");

        const __half* As = sh + (it % GNST) * STAGE_H;
        const __half* Bs = As + 128 * ASTR;

        #pragma unroll
        for (int kb = 0; kb < HBK; kb += 16) {
            unsigned a[2][4], b[8][2];
            ldsm4(a[0], &As[arow_l * ASTR + kb + acol_l]);
            ldsm4(a[1], &As[(arow_l + 16) * ASTR + kb + acol_l]);
            #pragma unroll
            for (int ntp = 0; ntp < 4; ntp++) {
                unsigned t4[4];
                ldsm4t(t4, &Bs[(kb + brow_l) * BSTR + bcol_l + ntp * 16]);
                b[2 * ntp][0]     = t4[0]; b[2 * ntp][1]     = t4[1];
                b[2 * ntp + 1][0] = t4[2]; b[2 * ntp + 1][1] = t4[3];
            }
            #pragma unroll
            for (int mt = 0; mt < 2; mt++)
                #pragma unroll
                for (int nt = 0; nt < 8; nt++)
                    mma16(acc[mt][nt], a[mt], b[nt]);
        }
    }

    // epilogue
    #pragma unroll
    for (int mt = 0; mt < 2; mt++) {
        const int r0 = m0 + wm * 32 + mt * 16 + g;
        const int r1 = r0 + 8;
        #pragma unroll
        for (int nt = 0; nt < 8; nt++) {
            const int c = n0 + wn * 64 + nt * 8 + tig * 2;
            const float b0 = bias[c], b1 = bias[c + 1];
            float v0 = acc[mt][nt][0] + b0;
            float v1 = acc[mt][nt][1] + b1;
            float v2 = acc[mt][nt][2] + b0;
            float v3 = acc[mt][nt][3] + b1;
            if (OP == 1) {
                float* Cf = (float*)Cv;
                const float2 ra = *reinterpret_cast<const float2*>(res + (size_t)r0 * N + c);
                const float2 rb = *reinterpret_cast<const float2*>(res + (size_t)r1 * N + c);
                *reinterpret_cast<float2*>(Cf + (size_t)r0 * N + c) = make_float2(v0 + ra.x, v1 + ra.y);
                *reinterpret_cast<float2*>(Cf + (size_t)r1 * N + c) = make_float2(v2 + rb.x, v3 + rb.y);
            } else {
                if (OP == 2) {
                    v0 = 0.5f * v0 * (1.0f + erff(v0 * 0.70710678118654752f));
                    v1 = 0.5f * v1 * (1.0f + erff(v1 * 0.70710678118654752f));
                    v2 = 0.5f * v2 * (1.0f + erff(v2 * 0.70710678118654752f));
                    v3 = 0.5f * v3 * (1.0f + erff(v3 * 0.70710678118654752f));
                }
                __half* Ch = (__half*)Cv;
                *reinterpret_cast<unsigned*>(Ch + (size_t)r0 * N + c) = h2u(__floats2half2_rn(v0, v1));
                *reinterpret_cast<unsigned*>(Ch + (size_t)r1 * N + c) = h2u(__floats2half2_rn(v2, v3));
            }
        }
    }
}

// ---------------- split qkv, L2-normalize q,k; relayout to [H,L,64] (fp16) ----
__global__ __launch_bounds__(256) void qkvnorm_kernel(
    const __half* __restrict__ qkv, __half* __restrict__ Q,
    __half* __restrict__ Km, __half* __restrict__ V)
{
    int gw   = (blockIdx.x * blockDim.x + threadIdx.x) >> 5;
    int lane = threadIdx.x & 31;
    int l = gw >> 4;
    int h = gw & 15;

    const __half* base = qkv + (size_t)l * (3 * DM);
    size_t oidx = ((size_t)h * SEQ + l) * HD + lane * 2;

    float2 qv = __half22float2(*reinterpret_cast<const __half2*>(base + h * HD + lane * 2));
    float ssq = qv.x * qv.x + qv.y * qv.y;
    #pragma unroll
    for (int o = 16; o > 0; o >>= 1) ssq += __shfl_xor_sync(0xffffffffu, ssq, o);
    float scq = 0.125f / fmaxf(sqrtf(ssq), 1e-12f);
    *reinterpret_cast<unsigned*>(Q + oidx) = h2u(__floats2half2_rn(qv.x * scq, qv.y * scq));

    float2 kv = __half22float2(*reinterpret_cast<const __half2*>(base + DM + h * HD + lane * 2));
    float ssk = kv.x * kv.x + kv.y * kv.y;
    #pragma unroll
    for (int o = 16; o > 0; o >>= 1) ssk += __shfl_xor_sync(0xffffffffu, ssk, o);
    float sck = 1.0f / fmaxf(sqrtf(ssk), 1e-12f);
    *reinterpret_cast<unsigned*>(Km + oidx) = h2u(__floats2half2_rn(kv.x * sck, kv.y * sck));

    *reinterpret_cast<const unsigned*>(base + 2 * DM + h * HD + lane * 2);
    *reinterpret_cast<unsigned*>(V + oidx) =
        *reinterpret_cast<const unsigned*>(base + 2 * DM + h * HD + lane * 2);
}

// ---------------- fp16 MMA attention ------------------------------------------
// grid (SEQ/128, NH), 256 thr = 8 warps x 16 query rows. Clip => no online max.
// fp16 trick: S c-fragment layout == P a-fragment layout (no shuffles).
#define QSTR 72   // halves (144B = 36 words === 4 mod 32)
__global__ __launch_bounds__(256) void attn_h_kernel(
    const __half* __restrict__ Q, const __half* __restrict__ Km,
    const __half* __restrict__ V, const float* __restrict__ lcc,
    __half* __restrict__ out)
{
    __shared__ __align__(16) __half pool[128 * QSTR];
    __shared__ float lccs[64];
    __half* Qs = pool;                  // [128][QSTR]
    __half* Ks = pool;                  // [64][QSTR]
    __half* Vs = pool + 64 * QSTR;      // [64][QSTR]

    const int h    = blockIdx.y;
    const int m0   = blockIdx.x * 128;
    const int tid  = threadIdx.x;
    const int lane = tid & 31;
    const int warp = tid >> 5;
    const int g    = lane >> 2;
    const int tig  = lane & 3;
    const int lt   = lane >> 3;
    const int li   = lane & 7;

    // stage Q tile (half) into smem
    {
        const __half* Qg = Q + ((size_t)h * SEQ + m0) * HD;
        #pragma unroll
        for (int t = 0; t < 4; t++) {
            int idx = t * 256 + tid;          // 1024 16B chunks
            int row = idx >> 3;
            int off = (idx & 7) * 8;
            *reinterpret_cast<uint4*>(&Qs[row * QSTR + off]) =
                *reinterpret_cast<const uint4*>(Qg + (size_t)row * HD + off);
        }
    }
    __syncthreads();

    // Q a-fragments: 4 k16 chunks over d=64
    unsigned qa[4][4];
    {
        const int qrow = warp * 16 + (lt & 1) * 8 + li;
        const int qcol = (lt >> 1) * 8;
        #pragma unroll
        for (int kc = 0; kc < 4; kc++)
            ldsm4(qa[kc], &Qs[qrow * QSTR + kc * 16 + qcol]);
    }

    const float rb0 = lcc[m0 + warp * 16 + g]     * 0.05f;
    const float rb1 = lcc[m0 + warp * 16 + 8 + g] * 0.05f;

    float o[8][4];
    #pragma unroll
    for (int nt = 0; nt < 8; nt++)
        #pragma unroll
        for (int i = 0; i < 4; i++) o[nt][i] = 0.0f;
    float d0 = 0.0f, d1 = 0.0f;

    for (int kt = 0; kt < SEQ; kt += 64) {
        __syncthreads();   // previous tile consumed / Q frags extracted
        {
            const __half* Kg = Km + ((size_t)h * SEQ + kt) * HD;
            const __half* Vg = V  + ((size_t)h * SEQ + kt) * HD;
            #pragma unroll
            for (int t = 0; t < 2; t++) {
                int idx = t * 256 + tid;      // 512 chunks per array
                int row = idx >> 3;
                int off = (idx & 7) * 8;
                *reinterpret_cast<uint4*>(&Ks[row * QSTR + off]) =
                    *reinterpret_cast<const uint4*>(Kg + (size_t)row * HD + off);
                *reinterpret_cast<uint4*>(&Vs[row * QSTR + off]) =
                    *reinterpret_cast<const uint4*>(Vg + (size_t)row * HD + off);
            }
            if (tid < 64) lccs[tid] = lcc[kt + tid] * 0.05f;
        }
        __syncthreads();

        // ---- S = Q @ K^T : 16x64 per warp (32 MMAs) ----
        float s[8][4];
        #pragma unroll
        for (int nt = 0; nt < 8; nt++)
            #pragma unroll
            for (int i = 0; i < 4; i++) s[nt][i] = 0.0f;

        #pragma unroll
        for (int kc = 0; kc < 4; kc++) {
            #pragma unroll
            for (int nt = 0; nt < 8; nt++) {
                unsigned b[2];
                b[0] = *reinterpret_cast<const unsigned*>(&Ks[(nt * 8 + g) * QSTR + kc * 16 + tig * 2]);
                b[1] = *reinterpret_cast<const unsigned*>(&Ks[(nt * 8 + g) * QSTR + kc * 16 + tig * 2 + 8]);
                mma16(s[nt], qa[kc], b);
            }
        }

        // ---- softmax numerators (fp16-rounded; denom from same rounding) ----
        unsigned pa[8][2];
        #pragma unroll
        for (int nt = 0; nt < 8; nt++) {
            float cb0 = lccs[nt * 8 + tig * 2];
            float cb1 = lccs[nt * 8 + tig * 2 + 1];
            float v0 = s[nt][0] + rb0 + cb0;
            float v1 = s[nt][1] + rb0 + cb1;
            float v2 = s[nt][2] + rb1 + cb0;
            float v3 = s[nt][3] + rb1 + cb1;
            v0 = fminf(10.0f, fmaxf(-10.0f, v0));
            v1 = fminf(10.0f, fmaxf(-10.0f, v1));
            v2 = fminf(10.0f, fmaxf(-10.0f, v2));
            v3 = fminf(10.0f, fmaxf(-10.0f, v3));
            __half2 p01 = __floats2half2_rn(__expf(v0), __expf(v1));
            __half2 p23 = __floats2half2_rn(__expf(v2), __expf(v3));
            pa[nt][0] = h2u(p01);
            pa[nt][1] = h2u(p23);
            float2 f01 = __half22float2(p01);
            float2 f23 = __half22float2(p23);
            d0 += f01.x + f01.y;
            d1 += f23.x + f23.y;
        }

        // ---- O += P @ V (32 MMAs, no shuffles) ----
        #pragma unroll
        for (int kc = 0; kc < 4; kc++) {
            unsigned a[4];
            a[0] = pa[2 * kc][0];
            a[1] = pa[2 * kc][1];
            a[2] = pa[2 * kc + 1][0];
            a[3] = pa[2 * kc + 1][1];
            unsigned vb[8][2];
            #pragma unroll
            for (int ntp = 0; ntp < 4; ntp++) {
                unsigned t4[4];
                ldsm4t(t4, &Vs[(kc * 16 + (lt & 1) * 8 + li) * QSTR + (ntp * 2 + (lt >> 1)) * 8]);
                vb[2 * ntp][0]     = t4[0]; vb[2 * ntp][1]     = t4[1];
                vb[2 * ntp + 1][0] = t4[2]; vb[2 * ntp + 1][1] = t4[3];
            }
            #pragma unroll
            for (int nt = 0; nt < 8; nt++)
                mma16(o[nt], a, vb[nt]);
        }
    }

    d0 += __shfl_xor_sync(0xffffffffu, d0, 1);
    d0 += __shfl_xor_sync(0xffffffffu, d0, 2);
    d1 += __shfl_xor_sync(0xffffffffu, d1, 1);
    d1 += __shfl_xor_sync(0xffffffffu, d1, 2);
    const float inv0 = 1.0f / d0;
    const float inv1 = 1.0f / d1;

    const int r0 = m0 + warp * 16 + g;
    const int r1 = r0 + 8;
    #pragma unroll
    for (int nt = 0; nt < 8; nt++) {
        const int c = h * HD + nt * 8 + tig * 2;
        *reinterpret_cast<unsigned*>(out + (size_t)r0 * DM + c) =
            h2u(__floats2half2_rn(o[nt][0] * inv0, o[nt][1] * inv0));
        *reinterpret_cast<unsigned*>(out + (size_t)r1 * DM + c) =
            h2u(__floats2half2_rn(o[nt][2] * inv1, o[nt][3] * inv1));
    }
}

// ---------------- launch --------------------------------------------------------
extern "C" void kernel_launch(void* const* d_in, const int* in_sizes, int n_in,
                              void* d_out, int out_size)
{
    const float* x     = (const float*)d_in[0];
    const float* lcc   = (const float*)d_in[1];
    const float* w_qkv = (const float*)d_in[2];
    const float* b_qkv = (const float*)d_in[3];
    const float* w_out = (const float*)d_in[4];
    const float* b_out = (const float*)d_in[5];
    const float* ln1_g = (const float*)d_in[6];
    const float* ln1_b = (const float*)d_in[7];
    const float* ln2_g = (const float*)d_in[8];
    const float* ln2_b = (const float*)d_in[9];
    const float* w_ff1 = (const float*)d_in[10];
    const float* b_ff1 = (const float*)d_in[11];
    const float* w_ff2 = (const float*)d_in[12];
    const float* b_ff2 = (const float*)d_in[13];
    float* out = (float*)d_out;

    __half *normed, *qkv, *q, *k, *v, *attn, *normed2, *ffh;
    __half *wqkv_h, *wout_h, *wff1_h, *wff2_h;
    float *x2;
    cudaGetSymbolAddress((void**)&normed,  g_normed);
    cudaGetSymbolAddress((void**)&qkv,     g_qkv);
    cudaGetSymbolAddress((void**)&q,       g_q);
    cudaGetSymbolAddress((void**)&k,       g_k);
    cudaGetSymbolAddress((void**)&v,       g_v);
    cudaGetSymbolAddress((void**)&attn,    g_attn);
    cudaGetSymbolAddress((void**)&x2,      g_x2);
    cudaGetSymbolAddress((void**)&normed2, g_normed2);
    cudaGetSymbolAddress((void**)&ffh,     g_ffh);
    cudaGetSymbolAddress((void**)&wqkv_h,  g_wqkv_h);
    cudaGetSymbolAddress((void**)&wout_h,  g_wout_h);
    cudaGetSymbolAddress((void**)&wff1_h,  g_wff1_h);
    cudaGetSymbolAddress((void**)&wff2_h,  g_wff2_h);

    const int smem = GNST * STAGE_H * 2;
    cudaFuncSetAttribute(hgemm<0>, cudaFuncAttributeMaxDynamicSharedMemorySize, smem);
    cudaFuncSetAttribute(hgemm<1>, cudaFuncAttributeMaxDynamicSharedMemorySize, smem);
    cudaFuncSetAttribute(hgemm<2>, cudaFuncAttributeMaxDynamicSharedMemorySize, smem);

    // 0. convert all weights to fp16 (single launch)
    cvt_all_kernel<<<296, 256>>>(
        w_qkv, wqkv_h, DM * 3 * DM / 4,
        w_out, wout_h, DM * DM / 4,
        w_ff1, wff1_h, DM * DFF / 4,
        w_ff2, wff2_h, DFF * DM / 4);

    // 1. LN1 (fp16 output)
    ln_kernel<<<SEQ, 256>>>(x, ln1_g, ln1_b, normed);
    // 2. QKV projection [2048,1024]@[1024,3072]
    hgemm<0><<<dim3(SEQ / 128, 3 * DM / 128), 256, smem>>>(
        normed, wqkv_h, b_qkv, nullptr, qkv, SEQ, 3 * DM, DM);
    // 3. split + cosine-normalize + relayout (fp16)
    qkvnorm_kernel<<<(SEQ * NH * 32) / 256, 256>>>(qkv, q, k, v);
    // 4. attention (fp16 MMA)
    attn_h_kernel<<<dim3(SEQ / 128, NH), 256>>>(q, k, v, lcc, attn);
    // 5. out projection + residual (fp32 out)
    hgemm<1><<<dim3(SEQ / 128, DM / 128), 256, smem>>>(
        attn, wout_h, b_out, x, x2, SEQ, DM, DM);
    // 6. LN2 (fp16 output)
    ln_kernel<<<SEQ, 256>>>(x2, ln2_g, ln2_b, normed2);
    // 7. FF1 + exact GELU (fp16 output)
    hgemm<2><<<dim3(SEQ / 128, DFF / 128), 256, smem>>>(
        normed2, wff1_h, b_ff1, nullptr, ffh, SEQ, DFF, DM);
    // 8. FF2 + residual -> out (fp32)
    hgemm<1><<<dim3(SEQ / 128, DM / 128), 256, smem>>>(
        ffh, wff2_h, b_ff2, x2, out, SEQ, DM, DFF);
}

// round 9
// speedup vs baseline: 2.1892x; 1.0110x over previous
#include <cuda_runtime.h>
#include <cuda_fp16.h>
#include <cstdint>
#include <math.h>

#define SEQ  2048
#define DM   1024
#define NH   16
#define HD   64
#define DFF  4096

// ---------------- scratch (no allocation allowed) ----------------
__device__ __half g_normed [SEQ * DM];
__device__ __half g_qkv    [SEQ * 3 * DM];
__device__ __half g_q      [NH * SEQ * HD];
__device__ __half g_k      [NH * SEQ * HD];
__device__ __half g_v      [NH * SEQ * HD];
__device__ __half g_attn   [SEQ * DM];
__device__ float  g_x2     [SEQ * DM];
__device__ __half g_normed2[SEQ * DM];
__device__ __half g_ffh    [SEQ * DFF];
// fp16 weight copies
__device__ __half g_wqkv_h [DM * 3 * DM];
__device__ __half g_wout_h [DM * DM];
__device__ __half g_wff1_h [DM * DFF];
__device__ __half g_wff2_h [DFF * DM];

// ---------------- helpers ----------------
__device__ __forceinline__ unsigned h2u(__half2 h) { return *reinterpret_cast<unsigned*>(&h); }

__device__ __forceinline__ void mma16(float* d, const unsigned* a, const unsigned* b) {
    asm volatile(
        "mma.sync.aligned.m16n8k16.row.col.f32.f16.f16.f32 "
        "{%0,%1,%2,%3}, {%4,%5,%6,%7}, {%8,%9}, {%0,%1,%2,%3};\n"
        : "+f"(d[0]), "+f"(d[1]), "+f"(d[2]), "+f"(d[3])
        : "r"(a[0]), "r"(a[1]), "r"(a[2]), "r"(a[3]), "r"(b[0]), "r"(b[1]));
}
__device__ __forceinline__ void cp16(void* sdst, const void* gsrc) {
    unsigned int d = (unsigned int)__cvta_generic_to_shared(sdst);
    asm volatile("cp.async.cg.shared.global [%0], [%1], 16;\n" :: "r"(d), "l"(gsrc));
}
__device__ __forceinline__ void ldsm4(unsigned* r, const void* saddr) {
    unsigned int ad = (unsigned int)__cvta_generic_to_shared(saddr);
    asm volatile("ldmatrix.sync.aligned.m8n8.x4.shared.b16 {%0,%1,%2,%3}, [%4];\n"
        : "=r"(r[0]), "=r"(r[1]), "=r"(r[2]), "=r"(r[3]) : "r"(ad));
}
__device__ __forceinline__ void ldsm4t(unsigned* r, const void* saddr) {
    unsigned int ad = (unsigned int)__cvta_generic_to_shared(saddr);
    asm volatile("ldmatrix.sync.aligned.m8n8.x4.trans.shared.b16 {%0,%1,%2,%3}, [%4];\n"
        : "=r"(r[0]), "=r"(r[1]), "=r"(r[2]), "=r"(r[3]) : "r"(ad));
}

// ---------------- fused weight fp32 -> fp16 convert ----------------
__global__ __launch_bounds__(256) void cvt_all_kernel(
    const float* __restrict__ s0, __half* __restrict__ d0, int n0,
    const float* __restrict__ s1, __half* __restrict__ d1, int n1,
    const float* __restrict__ s2, __half* __restrict__ d2, int n2,
    const float* __restrict__ s3, __half* __restrict__ d3, int n3)
{
    int i = blockIdx.x * blockDim.x + threadIdx.x;
    int stride = gridDim.x * blockDim.x;
    #define CVT_LOOP(S, D, N) \
    for (int j = i; j < N; j += stride) { \
        float4 v = reinterpret_cast<const float4*>(S)[j]; \
        __half2 lo = __floats2half2_rn(v.x, v.y); \
        __half2 hi = __floats2half2_rn(v.z, v.w); \
        reinterpret_cast<uint2*>(D)[j] = make_uint2(h2u(lo), h2u(hi)); \
    }
    CVT_LOOP(s0, d0, n0) CVT_LOOP(s1, d1, n1) CVT_LOOP(s2, d2, n2) CVT_LOOP(s3, d3, n3)
    #undef CVT_LOOP
}

// ---------------- LayerNorm (fp16 output: feeds GEMM A) ----------------
__global__ __launch_bounds__(256) void ln_kernel(
    const float* __restrict__ x, const float* __restrict__ g,
    const float* __restrict__ b, __half* __restrict__ out)
{
    int row = blockIdx.x;
    int tid = threadIdx.x;
    const float* xr = x + (size_t)row * DM;
    float4 xv = reinterpret_cast<const float4*>(xr)[tid];
    float s  = xv.x + xv.y + xv.z + xv.w;
    float sq = xv.x*xv.x + xv.y*xv.y + xv.z*xv.z + xv.w*xv.w;

    __shared__ float sh1[256], sh2[256];
    sh1[tid] = s; sh2[tid] = sq;
    __syncthreads();
    #pragma unroll
    for (int o = 128; o > 0; o >>= 1) {
        if (tid < o) { sh1[tid] += sh1[tid + o]; sh2[tid] += sh2[tid + o]; }
        __syncthreads();
    }
    float mu   = sh1[0] * (1.0f / DM);
    float var  = sh2[0] * (1.0f / DM) - mu * mu;
    float rstd = rsqrtf(var + 1e-5f);

    float4 gv = reinterpret_cast<const float4*>(g)[tid];
    float4 bv = reinterpret_cast<const float4*>(b)[tid];
    __half2 lo = __floats2half2_rn((xv.x - mu) * rstd * gv.x + bv.x,
                                   (xv.y - mu) * rstd * gv.y + bv.y);
    __half2 hi = __floats2half2_rn((xv.z - mu) * rstd * gv.z + bv.z,
                                   (xv.w - mu) * rstd * gv.w + bv.w);
    reinterpret_cast<uint2*>(out + (size_t)row * DM)[tid] = make_uint2(h2u(lo), h2u(hi));
}

// ---------------- fp16 MMA GEMM: 128x128 block, 8 warps (4x2), BK=32 ---------
#define ASTR 40
#define BSTR 136
#define HBK  32
#define STAGE_H (128 * ASTR + HBK * BSTR)
#define GNST 3

template<int OP>
__global__ __launch_bounds__(256) void hgemm(
    const __half* __restrict__ A, const __half* __restrict__ B,
    const float* __restrict__ bias, const float* __restrict__ res,
    void* __restrict__ Cv, int M, int N, int K)
{
    extern __shared__ __half sh[];

    const int tid  = threadIdx.x;
    const int lane = tid & 31;
    const int warp = tid >> 5;
    const int g    = lane >> 2;
    const int tig  = lane & 3;
    const int wm   = warp >> 1;
    const int wn   = warp & 1;
    const int m0   = blockIdx.x * 128;
    const int n0   = blockIdx.y * 128;

    const int lt = lane >> 3;
    const int li = lane & 7;
    const int arow_l = wm * 32 + (lt & 1) * 8 + li;
    const int acol_l = (lt >> 1) * 8;
    const int brow_l = (lt & 1) * 8 + li;
    const int bcol_l = wn * 64 + (lt >> 1) * 8;

    float acc[2][8][4];
    #pragma unroll
    for (int mt = 0; mt < 2; mt++)
        #pragma unroll
        for (int nt = 0; nt < 8; nt++)
            #pragma unroll
            for (int i = 0; i < 4; i++) acc[mt][nt][i] = 0.0f;

    const int nsteps = K >> 5;

    #pragma unroll
    for (int s = 0; s < GNST - 1; s++) {
        __half* As = sh + s * STAGE_H;
        __half* Bs = As + 128 * ASTR;
        #pragma unroll
        for (int t = 0; t < 2; t++) {
            int idx = t * 256 + tid;
            int arw = idx >> 2, aof = (idx & 3) * 8;
            cp16(&As[arw * ASTR + aof], A + (size_t)(m0 + arw) * K + s * HBK + aof);
            int brw = idx >> 4, bof = (idx & 15) * 8;
            cp16(&Bs[brw * BSTR + bof], B + (size_t)(s * HBK + brw) * N + n0 + bof);
        }
        asm volatile("cp.async.commit_group;\n");
    }

    for (int it = 0; it < nsteps; it++) {
        asm volatile("cp.async.wait_group %0;\n" :: "n"(GNST - 2));
        __syncthreads();

        if (it + GNST - 1 < nsteps) {
            const int s  = (it + GNST - 1) % GNST;
            const int kt = (it + GNST - 1) * HBK;
            __half* As = sh + s * STAGE_H;
            __half* Bs = As + 128 * ASTR;
            #pragma unroll
            for (int t = 0; t < 2; t++) {
                int idx = t * 256 + tid;
                int arw = idx >> 2, aof = (idx & 3) * 8;
                cp16(&As[arw * ASTR + aof], A + (size_t)(m0 + arw) * K + kt + aof);
                int brw = idx >> 4, bof = (idx & 15) * 8;
                cp16(&Bs[brw * BSTR + bof], B + (size_t)(kt + brw) * N + n0 + bof);
            }
        }
        asm volatile("cp.async.commit_group;\n");

        const __half* As = sh + (it % GNST) * STAGE_H;
        const __half* Bs = As + 128 * ASTR;

        #pragma unroll
        for (int kb = 0; kb < HBK; kb += 16) {
            unsigned a[2][4], b[8][2];
            ldsm4(a[0], &As[arow_l * ASTR + kb + acol_l]);
            ldsm4(a[1], &As[(arow_l + 16) * ASTR + kb + acol_l]);
            #pragma unroll
            for (int ntp = 0; ntp < 4; ntp++) {
                unsigned t4[4];
                ldsm4t(t4, &Bs[(kb + brow_l) * BSTR + bcol_l + ntp * 16]);
                b[2 * ntp][0]     = t4[0]; b[2 * ntp][1]     = t4[1];
                b[2 * ntp + 1][0] = t4[2]; b[2 * ntp + 1][1] = t4[3];
            }
            #pragma unroll
            for (int mt = 0; mt < 2; mt++)
                #pragma unroll
                for (int nt = 0; nt < 8; nt++)
                    mma16(acc[mt][nt], a[mt], b[nt]);
        }
    }

    #pragma unroll
    for (int mt = 0; mt < 2; mt++) {
        const int r0 = m0 + wm * 32 + mt * 16 + g;
        const int r1 = r0 + 8;
        #pragma unroll
        for (int nt = 0; nt < 8; nt++) {
            const int c = n0 + wn * 64 + nt * 8 + tig * 2;
            const float b0 = bias[c], b1 = bias[c + 1];
            float v0 = acc[mt][nt][0] + b0;
            float v1 = acc[mt][nt][1] + b1;
            float v2 = acc[mt][nt][2] + b0;
            float v3 = acc[mt][nt][3] + b1;
            if (OP == 1) {
                float* Cf = (float*)Cv;
                const float2 ra = *reinterpret_cast<const float2*>(res + (size_t)r0 * N + c);
                const float2 rb = *reinterpret_cast<const float2*>(res + (size_t)r1 * N + c);
                *reinterpret_cast<float2*>(Cf + (size_t)r0 * N + c) = make_float2(v0 + ra.x, v1 + ra.y);
                *reinterpret_cast<float2*>(Cf + (size_t)r1 * N + c) = make_float2(v2 + rb.x, v3 + rb.y);
            } else {
                if (OP == 2) {
                    v0 = 0.5f * v0 * (1.0f + erff(v0 * 0.70710678118654752f));
                    v1 = 0.5f * v1 * (1.0f + erff(v1 * 0.70710678118654752f));
                    v2 = 0.5f * v2 * (1.0f + erff(v2 * 0.70710678118654752f));
                    v3 = 0.5f * v3 * (1.0f + erff(v3 * 0.70710678118654752f));
                }
                __half* Ch = (__half*)Cv;
                *reinterpret_cast<unsigned*>(Ch + (size_t)r0 * N + c) = h2u(__floats2half2_rn(v0, v1));
                *reinterpret_cast<unsigned*>(Ch + (size_t)r1 * N + c) = h2u(__floats2half2_rn(v2, v3));
            }
        }
    }
}

// ---------------- split qkv, L2-normalize q,k; relayout to [H,L,64] (fp16) ----
__global__ __launch_bounds__(256) void qkvnorm_kernel(
    const __half* __restrict__ qkv, __half* __restrict__ Q,
    __half* __restrict__ Km, __half* __restrict__ V)
{
    int gw   = (blockIdx.x * blockDim.x + threadIdx.x) >> 5;
    int lane = threadIdx.x & 31;
    int l = gw >> 4;
    int h = gw & 15;

    const __half* base = qkv + (size_t)l * (3 * DM);
    size_t oidx = ((size_t)h * SEQ + l) * HD + lane * 2;

    float2 qv = __half22float2(*reinterpret_cast<const __half2*>(base + h * HD + lane * 2));
    float ssq = qv.x * qv.x + qv.y * qv.y;
    #pragma unroll
    for (int o = 16; o > 0; o >>= 1) ssq += __shfl_xor_sync(0xffffffffu, ssq, o);
    float scq = 0.125f / fmaxf(sqrtf(ssq), 1e-12f);
    *reinterpret_cast<unsigned*>(Q + oidx) = h2u(__floats2half2_rn(qv.x * scq, qv.y * scq));

    float2 kv = __half22float2(*reinterpret_cast<const __half2*>(base + DM + h * HD + lane * 2));
    float ssk = kv.x * kv.x + kv.y * kv.y;
    #pragma unroll
    for (int o = 16; o > 0; o >>= 1) ssk += __shfl_xor_sync(0xffffffffu, ssk, o);
    float sck = 1.0f / fmaxf(sqrtf(ssk), 1e-12f);
    *reinterpret_cast<unsigned*>(Km + oidx) = h2u(__floats2half2_rn(kv.x * sck, kv.y * sck));

    *reinterpret_cast<unsigned*>(V + oidx) =
        *reinterpret_cast<const unsigned*>(base + 2 * DM + h * HD + lane * 2);
}

// ---------------- fp16 MMA attention, double-buffered cp.async K/V ------------
// grid (SEQ/128, NH), 256 thr = 8 warps x 16 query rows. Clip => no online max.
// Dynamic smem: Q[128][QSTR] + K[2][64][QSTR] + V[2][64][QSTR]  (~55 KB)
#define QSTR 72
#define KVSTAGE (64 * QSTR)
__global__ __launch_bounds__(256) void attn_h_kernel(
    const __half* __restrict__ Q, const __half* __restrict__ Km,
    const __half* __restrict__ V, const float* __restrict__ lcc,
    __half* __restrict__ out)
{
    extern __shared__ __half apool[];
    __half* Qs = apool;                        // [128][QSTR]
    __half* Kb = apool + 128 * QSTR;           // [2][64][QSTR]
    __half* Vb = Kb + 2 * KVSTAGE;             // [2][64][QSTR]
    __shared__ float lccs[2][64];

    const int h    = blockIdx.y;
    const int m0   = blockIdx.x * 128;
    const int tid  = threadIdx.x;
    const int lane = tid & 31;
    const int warp = tid >> 5;
    const int g    = lane >> 2;
    const int tig  = lane & 3;
    const int lt   = lane >> 3;
    const int li   = lane & 7;

    const __half* Kg = Km + (size_t)h * SEQ * HD;
    const __half* Vg = V  + (size_t)h * SEQ * HD;

    // K/V tile loader (cp.async): stage sb, key offset kt
    #define LOAD_KV(sb, kt) do { \
        __half* Kd = Kb + (sb) * KVSTAGE; \
        __half* Vd = Vb + (sb) * KVSTAGE; \
        _Pragma("unroll") \
        for (int t = 0; t < 2; t++) { \
            int idx = t * 256 + tid; \
            int row = idx >> 3; \
            int off = (idx & 7) * 8; \
            cp16(&Kd[row * QSTR + off], Kg + (size_t)((kt) + row) * HD + off); \
            cp16(&Vd[row * QSTR + off], Vg + (size_t)((kt) + row) * HD + off); \
        } \
        asm volatile("cp.async.commit_group;\n"); \
        if (tid < 64) lccs[sb][tid] = lcc[(kt) + tid] * 0.05f; \
    } while (0)

    // stage 0 K/V load first (overlaps with Q staging)
    LOAD_KV(0, 0);

    // stage Q tile
    {
        const __half* Qg = Q + ((size_t)h * SEQ + m0) * HD;
        #pragma unroll
        for (int t = 0; t < 4; t++) {
            int idx = t * 256 + tid;
            int row = idx >> 3;
            int off = (idx & 7) * 8;
            *reinterpret_cast<uint4*>(&Qs[row * QSTR + off]) =
                *reinterpret_cast<const uint4*>(Qg + (size_t)row * HD + off);
        }
    }
    __syncthreads();

    unsigned qa[4][4];
    {
        const int qrow = warp * 16 + (lt & 1) * 8 + li;
        const int qcol = (lt >> 1) * 8;
        #pragma unroll
        for (int kc = 0; kc < 4; kc++)
            ldsm4(qa[kc], &Qs[qrow * QSTR + kc * 16 + qcol]);
    }

    const float rb0 = lcc[m0 + warp * 16 + g]     * 0.05f;
    const float rb1 = lcc[m0 + warp * 16 + 8 + g] * 0.05f;

    float o[8][4];
    #pragma unroll
    for (int nt = 0; nt < 8; nt++)
        #pragma unroll
        for (int i = 0; i < 4; i++) o[nt][i] = 0.0f;
    float d0 = 0.0f, d1 = 0.0f;

    for (int ti = 0; ti < SEQ / 64; ti++) {
        const int buf = ti & 1;
        __syncthreads();   // all warps done computing on buffer buf^1 (iter ti-1)
        if (ti + 1 < SEQ / 64) {
            LOAD_KV(buf ^ 1, (ti + 1) * 64);
        } else {
            asm volatile("cp.async.commit_group;\n");   // empty group keeps count aligned
        }
        asm volatile("cp.async.wait_group 1;\n");        // group for stage `buf` done
        __syncthreads();

        const __half* Ks = Kb + buf * KVSTAGE;
        const __half* Vs = Vb + buf * KVSTAGE;

        // ---- S = Q @ K^T ----
        float s[8][4];
        #pragma unroll
        for (int nt = 0; nt < 8; nt++)
            #pragma unroll
            for (int i = 0; i < 4; i++) s[nt][i] = 0.0f;

        #pragma unroll
        for (int kc = 0; kc < 4; kc++) {
            #pragma unroll
            for (int nt = 0; nt < 8; nt++) {
                unsigned b[2];
                b[0] = *reinterpret_cast<const unsigned*>(&Ks[(nt * 8 + g) * QSTR + kc * 16 + tig * 2]);
                b[1] = *reinterpret_cast<const unsigned*>(&Ks[(nt * 8 + g) * QSTR + kc * 16 + tig * 2 + 8]);
                mma16(s[nt], qa[kc], b);
            }
        }

        // ---- softmax numerators ----
        unsigned pa[8][2];
        #pragma unroll
        for (int nt = 0; nt < 8; nt++) {
            float cb0 = lccs[buf][nt * 8 + tig * 2];
            float cb1 = lccs[buf][nt * 8 + tig * 2 + 1];
            float v0 = s[nt][0] + rb0 + cb0;
            float v1 = s[nt][1] + rb0 + cb1;
            float v2 = s[nt][2] + rb1 + cb0;
            float v3 = s[nt][3] + rb1 + cb1;
            v0 = fminf(10.0f, fmaxf(-10.0f, v0));
            v1 = fminf(10.0f, fmaxf(-10.0f, v1));
            v2 = fminf(10.0f, fmaxf(-10.0f, v2));
            v3 = fminf(10.0f, fmaxf(-10.0f, v3));
            __half2 p01 = __floats2half2_rn(__expf(v0), __expf(v1));
            __half2 p23 = __floats2half2_rn(__expf(v2), __expf(v3));
            pa[nt][0] = h2u(p01);
            pa[nt][1] = h2u(p23);
            float2 f01 = __half22float2(p01);
            float2 f23 = __half22float2(p23);
            d0 += f01.x + f01.y;
            d1 += f23.x + f23.y;
        }

        // ---- O += P @ V ----
        #pragma unroll
        for (int kc = 0; kc < 4; kc++) {
            unsigned a[4];
            a[0] = pa[2 * kc][0];
            a[1] = pa[2 * kc][1];
            a[2] = pa[2 * kc + 1][0];
            a[3] = pa[2 * kc + 1][1];
            unsigned vb[8][2];
            #pragma unroll
            for (int ntp = 0; ntp < 4; ntp++) {
                unsigned t4[4];
                ldsm4t(t4, &Vs[(kc * 16 + (lt & 1) * 8 + li) * QSTR + (ntp * 2 + (lt >> 1)) * 8]);
                vb[2 * ntp][0]     = t4[0]; vb[2 * ntp][1]     = t4[1];
                vb[2 * ntp + 1][0] = t4[2]; vb[2 * ntp + 1][1] = t4[3];
            }
            #pragma unroll
            for (int nt = 0; nt < 8; nt++)
                mma16(o[nt], a, vb[nt]);
        }
    }
    #undef LOAD_KV

    d0 += __shfl_xor_sync(0xffffffffu, d0, 1);
    d0 += __shfl_xor_sync(0xffffffffu, d0, 2);
    d1 += __shfl_xor_sync(0xffffffffu, d1, 1);
    d1 += __shfl_xor_sync(0xffffffffu, d1, 2);
    const float inv0 = 1.0f / d0;
    const float inv1 = 1.0f / d1;

    const int r0 = m0 + warp * 16 + g;
    const int r1 = r0 + 8;
    #pragma unroll
    for (int nt = 0; nt < 8; nt++) {
        const int c = h * HD + nt * 8 + tig * 2;
        *reinterpret_cast<unsigned*>(out + (size_t)r0 * DM + c) =
            h2u(__floats2half2_rn(o[nt][0] * inv0, o[nt][1] * inv0));
        *reinterpret_cast<unsigned*>(out + (size_t)r1 * DM + c) =
            h2u(__floats2half2_rn(o[nt][2] * inv1, o[nt][3] * inv1));
    }
}

// ---------------- launch --------------------------------------------------------
extern "C" void kernel_launch(void* const* d_in, const int* in_sizes, int n_in,
                              void* d_out, int out_size)
{
    const float* x     = (const float*)d_in[0];
    const float* lcc   = (const float*)d_in[1];
    const float* w_qkv = (const float*)d_in[2];
    const float* b_qkv = (const float*)d_in[3];
    const float* w_out = (const float*)d_in[4];
    const float* b_out = (const float*)d_in[5];
    const float* ln1_g = (const float*)d_in[6];
    const float* ln1_b = (const float*)d_in[7];
    const float* ln2_g = (const float*)d_in[8];
    const float* ln2_b = (const float*)d_in[9];
    const float* w_ff1 = (const float*)d_in[10];
    const float* b_ff1 = (const float*)d_in[11];
    const float* w_ff2 = (const float*)d_in[12];
    const float* b_ff2 = (const float*)d_in[13];
    float* out = (float*)d_out;

    __half *normed, *qkv, *q, *k, *v, *attn, *normed2, *ffh;
    __half *wqkv_h, *wout_h, *wff1_h, *wff2_h;
    float *x2;
    cudaGetSymbolAddress((void**)&normed,  g_normed);
    cudaGetSymbolAddress((void**)&qkv,     g_qkv);
    cudaGetSymbolAddress((void**)&q,       g_q);
    cudaGetSymbolAddress((void**)&k,       g_k);
    cudaGetSymbolAddress((void**)&v,       g_v);
    cudaGetSymbolAddress((void**)&attn,    g_attn);
    cudaGetSymbolAddress((void**)&x2,      g_x2);
    cudaGetSymbolAddress((void**)&normed2, g_normed2);
    cudaGetSymbolAddress((void**)&ffh,     g_ffh);
    cudaGetSymbolAddress((void**)&wqkv_h,  g_wqkv_h);
    cudaGetSymbolAddress((void**)&wout_h,  g_wout_h);
    cudaGetSymbolAddress((void**)&wff1_h,  g_wff1_h);
    cudaGetSymbolAddress((void**)&wff2_h,  g_wff2_h);

    const int smem = GNST * STAGE_H * 2;
    cudaFuncSetAttribute(hgemm<0>, cudaFuncAttributeMaxDynamicSharedMemorySize, smem);
    cudaFuncSetAttribute(hgemm<1>, cudaFuncAttributeMaxDynamicSharedMemorySize, smem);
    cudaFuncSetAttribute(hgemm<2>, cudaFuncAttributeMaxDynamicSharedMemorySize, smem);

    const int asmem = (128 * QSTR + 4 * KVSTAGE) * 2;
    cudaFuncSetAttribute(attn_h_kernel, cudaFuncAttributeMaxDynamicSharedMemorySize, asmem);

    // 0. convert all weights to fp16 (single launch)
    cvt_all_kernel<<<296, 256>>>(
        w_qkv, wqkv_h, DM * 3 * DM / 4,
        w_out, wout_h, DM * DM / 4,
        w_ff1, wff1_h, DM * DFF / 4,
        w_ff2, wff2_h, DFF * DM / 4);

    // 1. LN1 (fp16 output)
    ln_kernel<<<SEQ, 256>>>(x, ln1_g, ln1_b, normed);
    // 2. QKV projection [2048,1024]@[1024,3072]
    hgemm<0><<<dim3(SEQ / 128, 3 * DM / 128), 256, smem>>>(
        normed, wqkv_h, b_qkv, nullptr, qkv, SEQ, 3 * DM, DM);
    // 3. split + cosine-normalize + relayout (fp16)
    qkvnorm_kernel<<<(SEQ * NH * 32) / 256, 256>>>(qkv, q, k, v);
    // 4. attention (fp16 MMA, pipelined K/V)
    attn_h_kernel<<<dim3(SEQ / 128, NH), 256, asmem>>>(q, k, v, lcc, attn);
    // 5. out projection + residual (fp32 out)
    hgemm<1><<<dim3(SEQ / 128, DM / 128), 256, smem>>>(
        attn, wout_h, b_out, x, x2, SEQ, DM, DM);
    // 6. LN2 (fp16 output)
    ln_kernel<<<SEQ, 256>>>(x2, ln2_g, ln2_b, normed2);
    // 7. FF1 + exact GELU (fp16 output)
    hgemm<2><<<dim3(SEQ / 128, DFF / 128), 256, smem>>>(
        normed2, wff1_h, b_ff1, nullptr, ffh, SEQ, DFF, DM);
    // 8. FF2 + residual -> out (fp32)
    hgemm<1><<<dim3(SEQ / 128, DM / 128), 256, smem>>>(
        ffh, wff2_h, b_ff2, x2, out, SEQ, DM, DFF);
}

// round 10
// speedup vs baseline: 2.2373x; 1.0220x over previous
#include <cuda_runtime.h>
#include <cuda_fp16.h>
#include <cstdint>
#include <math.h>

#define SEQ  2048
#define DM   1024
#define NH   16
#define HD   64
#define DFF  4096

// ---------------- scratch (no allocation allowed) ----------------
__device__ __half g_normed [SEQ * DM];
__device__ __half g_q      [NH * SEQ * HD];
__device__ __half g_k      [NH * SEQ * HD];
__device__ __half g_v      [NH * SEQ * HD];
__device__ __half g_attn   [SEQ * DM];
__device__ float  g_x2     [SEQ * DM];
__device__ __half g_normed2[SEQ * DM];
__device__ __half g_ffh    [SEQ * DFF];
// fp16 weight copies
__device__ __half g_wqkv_h [DM * 3 * DM];
__device__ __half g_wout_h [DM * DM];
__device__ __half g_wff1_h [DM * DFF];
__device__ __half g_wff2_h [DFF * DM];

// ---------------- helpers ----------------
__device__ __forceinline__ unsigned h2u(__half2 h) { return *reinterpret_cast<unsigned*>(&h); }

__device__ __forceinline__ void mma16(float* d, const unsigned* a, const unsigned* b) {
    asm volatile(
        "mma.sync.aligned.m16n8k16.row.col.f32.f16.f16.f32 "
        "{%0,%1,%2,%3}, {%4,%5,%6,%7}, {%8,%9}, {%0,%1,%2,%3};\n"
        : "+f"(d[0]), "+f"(d[1]), "+f"(d[2]), "+f"(d[3])
        : "r"(a[0]), "r"(a[1]), "r"(a[2]), "r"(a[3]), "r"(b[0]), "r"(b[1]));
}
__device__ __forceinline__ void cp16(void* sdst, const void* gsrc) {
    unsigned int d = (unsigned int)__cvta_generic_to_shared(sdst);
    asm volatile("cp.async.cg.shared.global [%0], [%1], 16;\n" :: "r"(d), "l"(gsrc));
}
__device__ __forceinline__ void ldsm4(unsigned* r, const void* saddr) {
    unsigned int ad = (unsigned int)__cvta_generic_to_shared(saddr);
    asm volatile("ldmatrix.sync.aligned.m8n8.x4.shared.b16 {%0,%1,%2,%3}, [%4];\n"
        : "=r"(r[0]), "=r"(r[1]), "=r"(r[2]), "=r"(r[3]) : "r"(ad));
}
__device__ __forceinline__ void ldsm4t(unsigned* r, const void* saddr) {
    unsigned int ad = (unsigned int)__cvta_generic_to_shared(saddr);
    asm volatile("ldmatrix.sync.aligned.m8n8.x4.trans.shared.b16 {%0,%1,%2,%3}, [%4];\n"
        : "=r"(r[0]), "=r"(r[1]), "=r"(r[2]), "=r"(r[3]) : "r"(ad));
}

// ---------------- fused weight fp32 -> fp16 convert ----------------
__global__ __launch_bounds__(256) void cvt_all_kernel(
    const float* __restrict__ s0, __half* __restrict__ d0, int n0,
    const float* __restrict__ s1, __half* __restrict__ d1, int n1,
    const float* __restrict__ s2, __half* __restrict__ d2, int n2,
    const float* __restrict__ s3, __half* __restrict__ d3, int n3)
{
    int i = blockIdx.x * blockDim.x + threadIdx.x;
    int stride = gridDim.x * blockDim.x;
    #define CVT_LOOP(S, D, N) \
    for (int j = i; j < N; j += stride) { \
        float4 v = reinterpret_cast<const float4*>(S)[j]; \
        __half2 lo = __floats2half2_rn(v.x, v.y); \
        __half2 hi = __floats2half2_rn(v.z, v.w); \
        reinterpret_cast<uint2*>(D)[j] = make_uint2(h2u(lo), h2u(hi)); \
    }
    CVT_LOOP(s0, d0, n0) CVT_LOOP(s1, d1, n1) CVT_LOOP(s2, d2, n2) CVT_LOOP(s3, d3, n3)
    #undef CVT_LOOP
}

// ---------------- LayerNorm (fp16 output: feeds GEMM A) ----------------
__global__ __launch_bounds__(256) void ln_kernel(
    const float* __restrict__ x, const float* __restrict__ g,
    const float* __restrict__ b, __half* __restrict__ out)
{
    int row = blockIdx.x;
    int tid = threadIdx.x;
    const float* xr = x + (size_t)row * DM;
    float4 xv = reinterpret_cast<const float4*>(xr)[tid];
    float s  = xv.x + xv.y + xv.z + xv.w;
    float sq = xv.x*xv.x + xv.y*xv.y + xv.z*xv.z + xv.w*xv.w;

    __shared__ float sh1[256], sh2[256];
    sh1[tid] = s; sh2[tid] = sq;
    __syncthreads();
    #pragma unroll
    for (int o = 128; o > 0; o >>= 1) {
        if (tid < o) { sh1[tid] += sh1[tid + o]; sh2[tid] += sh2[tid + o]; }
        __syncthreads();
    }
    float mu   = sh1[0] * (1.0f / DM);
    float var  = sh2[0] * (1.0f / DM) - mu * mu;
    float rstd = rsqrtf(var + 1e-5f);

    float4 gv = reinterpret_cast<const float4*>(g)[tid];
    float4 bv = reinterpret_cast<const float4*>(b)[tid];
    __half2 lo = __floats2half2_rn((xv.x - mu) * rstd * gv.x + bv.x,
                                   (xv.y - mu) * rstd * gv.y + bv.y);
    __half2 hi = __floats2half2_rn((xv.z - mu) * rstd * gv.z + bv.z,
                                   (xv.w - mu) * rstd * gv.w + bv.w);
    reinterpret_cast<uint2*>(out + (size_t)row * DM)[tid] = make_uint2(h2u(lo), h2u(hi));
}

// ---------------- fp16 MMA GEMM: 128x128 block, 8 warps (4x2), BK=32 ---------
// OP = 1: float C = A*B + bias + res (fp32 residual)
// OP = 2: half C = gelu(A*B + bias)
// OP = 3: QKV epilogue — per-(row,head) L2-normalize q,k; write [H,L,64] layout
#define ASTR 40
#define BSTR 136
#define HBK  32
#define STAGE_H (128 * ASTR + HBK * BSTR)
#define GNST 3

template<int OP>
__global__ __launch_bounds__(256) void hgemm(
    const __half* __restrict__ A, const __half* __restrict__ B,
    const float* __restrict__ bias, const float* __restrict__ res,
    void* __restrict__ Cv, __half* __restrict__ Qo, __half* __restrict__ Ko,
    __half* __restrict__ Vo, int M, int N, int K)
{
    extern __shared__ __half sh[];

    const int tid  = threadIdx.x;
    const int lane = tid & 31;
    const int warp = tid >> 5;
    const int g    = lane >> 2;
    const int tig  = lane & 3;
    const int wm   = warp >> 1;
    const int wn   = warp & 1;
    const int m0   = blockIdx.x * 128;
    const int n0   = blockIdx.y * 128;

    const int lt = lane >> 3;
    const int li = lane & 7;
    const int arow_l = wm * 32 + (lt & 1) * 8 + li;
    const int acol_l = (lt >> 1) * 8;
    const int brow_l = (lt & 1) * 8 + li;
    const int bcol_l = wn * 64 + (lt >> 1) * 8;

    float acc[2][8][4];
    #pragma unroll
    for (int mt = 0; mt < 2; mt++)
        #pragma unroll
        for (int nt = 0; nt < 8; nt++)
            #pragma unroll
            for (int i = 0; i < 4; i++) acc[mt][nt][i] = 0.0f;

    const int nsteps = K >> 5;

    #pragma unroll
    for (int s = 0; s < GNST - 1; s++) {
        __half* As = sh + s * STAGE_H;
        __half* Bs = As + 128 * ASTR;
        #pragma unroll
        for (int t = 0; t < 2; t++) {
            int idx = t * 256 + tid;
            int arw = idx >> 2, aof = (idx & 3) * 8;
            cp16(&As[arw * ASTR + aof], A + (size_t)(m0 + arw) * K + s * HBK + aof);
            int brw = idx >> 4, bof = (idx & 15) * 8;
            cp16(&Bs[brw * BSTR + bof], B + (size_t)(s * HBK + brw) * N + n0 + bof);
        }
        asm volatile("cp.async.commit_group;\n");
    }

    for (int it = 0; it < nsteps; it++) {
        asm volatile("cp.async.wait_group %0;\n" :: "n"(GNST - 2));
        __syncthreads();

        if (it + GNST - 1 < nsteps) {
            const int s  = (it + GNST - 1) % GNST;
            const int kt = (it + GNST - 1) * HBK;
            __half* As = sh + s * STAGE_H;
            __half* Bs = As + 128 * ASTR;
            #pragma unroll
            for (int t = 0; t < 2; t++) {
                int idx = t * 256 + tid;
                int arw = idx >> 2, aof = (idx & 3) * 8;
                cp16(&As[arw * ASTR + aof], A + (size_t)(m0 + arw) * K + kt + aof);
                int brw = idx >> 4, bof = (idx & 15) * 8;
                cp16(&Bs[brw * BSTR + bof], B + (size_t)(kt + brw) * N + n0 + bof);
            }
        }
        asm volatile("cp.async.commit_group;\n");

        const __half* As = sh + (it % GNST) * STAGE_H;
        const __half* Bs = As + 128 * ASTR;

        #pragma unroll
        for (int kb = 0; kb < HBK; kb += 16) {
            unsigned a[2][4], b[8][2];
            ldsm4(a[0], &As[arow_l * ASTR + kb + acol_l]);
            ldsm4(a[1], &As[(arow_l + 16) * ASTR + kb + acol_l]);
            #pragma unroll
            for (int ntp = 0; ntp < 4; ntp++) {
                unsigned t4[4];
                ldsm4t(t4, &Bs[(kb + brow_l) * BSTR + bcol_l + ntp * 16]);
                b[2 * ntp][0]     = t4[0]; b[2 * ntp][1]     = t4[1];
                b[2 * ntp + 1][0] = t4[2]; b[2 * ntp + 1][1] = t4[3];
            }
            #pragma unroll
            for (int mt = 0; mt < 2; mt++)
                #pragma unroll
                for (int nt = 0; nt < 8; nt++)
                    mma16(acc[mt][nt], a[mt], b[nt]);
        }
    }

    // ---------------- epilogue ----------------
    if (OP == 3) {
        // warp covers one 64-col head-group: grp = n0/64 + wn
        const int grp = (n0 >> 6) + wn;     // 0..47
        const int cls = grp >> 4;           // 0=q, 1=k, 2=v
        const int hh  = grp & 15;
        __half* Dst = (cls == 0) ? Qo : (cls == 1) ? Ko : Vo;

        #pragma unroll
        for (int mt = 0; mt < 2; mt++) {
            const int r0 = m0 + wm * 32 + mt * 16 + g;
            const int r1 = r0 + 8;
            float v[8][4];
            float ss0 = 0.0f, ss1 = 0.0f;
            #pragma unroll
            for (int nt = 0; nt < 8; nt++) {
                const int c = n0 + wn * 64 + nt * 8 + tig * 2;
                const float b0 = bias[c], b1 = bias[c + 1];
                v[nt][0] = acc[mt][nt][0] + b0;
                v[nt][1] = acc[mt][nt][1] + b1;
                v[nt][2] = acc[mt][nt][2] + b0;
                v[nt][3] = acc[mt][nt][3] + b1;
                ss0 += v[nt][0] * v[nt][0] + v[nt][1] * v[nt][1];
                ss1 += v[nt][2] * v[nt][2] + v[nt][3] * v[nt][3];
            }
            // reduce across the lane quad (tig = lane bits 0..1)
            ss0 += __shfl_xor_sync(0xffffffffu, ss0, 1);
            ss0 += __shfl_xor_sync(0xffffffffu, ss0, 2);
            ss1 += __shfl_xor_sync(0xffffffffu, ss1, 1);
            ss1 += __shfl_xor_sync(0xffffffffu, ss1, 2);
            float sc0 = 1.0f, sc1 = 1.0f;
            if (cls == 0) {
                sc0 = 0.125f / fmaxf(sqrtf(ss0), 1e-12f);
                sc1 = 0.125f / fmaxf(sqrtf(ss1), 1e-12f);
            } else if (cls == 1) {
                sc0 = 1.0f / fmaxf(sqrtf(ss0), 1e-12f);
                sc1 = 1.0f / fmaxf(sqrtf(ss1), 1e-12f);
            }
            __half* d0p = Dst + ((size_t)hh * SEQ + r0) * HD + tig * 2;
            __half* d1p = Dst + ((size_t)hh * SEQ + r1) * HD + tig * 2;
            #pragma unroll
            for (int nt = 0; nt < 8; nt++) {
                *reinterpret_cast<unsigned*>(d0p + nt * 8) =
                    h2u(__floats2half2_rn(v[nt][0] * sc0, v[nt][1] * sc0));
                *reinterpret_cast<unsigned*>(d1p + nt * 8) =
                    h2u(__floats2half2_rn(v[nt][2] * sc1, v[nt][3] * sc1));
            }
        }
        return;
    }

    #pragma unroll
    for (int mt = 0; mt < 2; mt++) {
        const int r0 = m0 + wm * 32 + mt * 16 + g;
        const int r1 = r0 + 8;
        #pragma unroll
        for (int nt = 0; nt < 8; nt++) {
            const int c = n0 + wn * 64 + nt * 8 + tig * 2;
            const float b0 = bias[c], b1 = bias[c + 1];
            float v0 = acc[mt][nt][0] + b0;
            float v1 = acc[mt][nt][1] + b1;
            float v2 = acc[mt][nt][2] + b0;
            float v3 = acc[mt][nt][3] + b1;
            if (OP == 1) {
                float* Cf = (float*)Cv;
                const float2 ra = *reinterpret_cast<const float2*>(res + (size_t)r0 * N + c);
                const float2 rb = *reinterpret_cast<const float2*>(res + (size_t)r1 * N + c);
                *reinterpret_cast<float2*>(Cf + (size_t)r0 * N + c) = make_float2(v0 + ra.x, v1 + ra.y);
                *reinterpret_cast<float2*>(Cf + (size_t)r1 * N + c) = make_float2(v2 + rb.x, v3 + rb.y);
            } else {
                if (OP == 2) {
                    v0 = 0.5f * v0 * (1.0f + erff(v0 * 0.70710678118654752f));
                    v1 = 0.5f * v1 * (1.0f + erff(v1 * 0.70710678118654752f));
                    v2 = 0.5f * v2 * (1.0f + erff(v2 * 0.70710678118654752f));
                    v3 = 0.5f * v3 * (1.0f + erff(v3 * 0.70710678118654752f));
                }
                __half* Ch = (__half*)Cv;
                *reinterpret_cast<unsigned*>(Ch + (size_t)r0 * N + c) = h2u(__floats2half2_rn(v0, v1));
                *reinterpret_cast<unsigned*>(Ch + (size_t)r1 * N + c) = h2u(__floats2half2_rn(v2, v3));
            }
        }
    }
}

// ---------------- fp16 MMA attention, double-buffered cp.async K/V ------------
#define QSTR 72
#define KVSTAGE (64 * QSTR)
__global__ __launch_bounds__(256) void attn_h_kernel(
    const __half* __restrict__ Q, const __half* __restrict__ Km,
    const __half* __restrict__ V, const float* __restrict__ lcc,
    __half* __restrict__ out)
{
    extern __shared__ __half apool[];
    __half* Qs = apool;
    __half* Kb = apool + 128 * QSTR;
    __half* Vb = Kb + 2 * KVSTAGE;
    __shared__ float lccs[2][64];

    const int h    = blockIdx.y;
    const int m0   = blockIdx.x * 128;
    const int tid  = threadIdx.x;
    const int lane = tid & 31;
    const int warp = tid >> 5;
    const int g    = lane >> 2;
    const int tig  = lane & 3;
    const int lt   = lane >> 3;
    const int li   = lane & 7;

    const __half* Kg = Km + (size_t)h * SEQ * HD;
    const __half* Vg = V  + (size_t)h * SEQ * HD;

    #define LOAD_KV(sb, kt) do { \
        __half* Kd = Kb + (sb) * KVSTAGE; \
        __half* Vd = Vb + (sb) * KVSTAGE; \
        _Pragma("unroll") \
        for (int t = 0; t < 2; t++) { \
            int idx = t * 256 + tid; \
            int row = idx >> 3; \
            int off = (idx & 7) * 8; \
            cp16(&Kd[row * QSTR + off], Kg + (size_t)((kt) + row) * HD + off); \
            cp16(&Vd[row * QSTR + off], Vg + (size_t)((kt) + row) * HD + off); \
        } \
        asm volatile("cp.async.commit_group;\n"); \
        if (tid < 64) lccs[sb][tid] = lcc[(kt) + tid] * 0.05f; \
    } while (0)

    LOAD_KV(0, 0);

    {
        const __half* Qg = Q + ((size_t)h * SEQ + m0) * HD;
        #pragma unroll
        for (int t = 0; t < 4; t++) {
            int idx = t * 256 + tid;
            int row = idx >> 3;
            int off = (idx & 7) * 8;
            *reinterpret_cast<uint4*>(&Qs[row * QSTR + off]) =
                *reinterpret_cast<const uint4*>(Qg + (size_t)row * HD + off);
        }
    }
    __syncthreads();

    unsigned qa[4][4];
    {
        const int qrow = warp * 16 + (lt & 1) * 8 + li;
        const int qcol = (lt >> 1) * 8;
        #pragma unroll
        for (int kc = 0; kc < 4; kc++)
            ldsm4(qa[kc], &Qs[qrow * QSTR + kc * 16 + qcol]);
    }

    const float rb0 = lcc[m0 + warp * 16 + g]     * 0.05f;
    const float rb1 = lcc[m0 + warp * 16 + 8 + g] * 0.05f;

    float o[8][4];
    #pragma unroll
    for (int nt = 0; nt < 8; nt++)
        #pragma unroll
        for (int i = 0; i < 4; i++) o[nt][i] = 0.0f;
    float d0 = 0.0f, d1 = 0.0f;

    for (int ti = 0; ti < SEQ / 64; ti++) {
        const int buf = ti & 1;
        __syncthreads();
        if (ti + 1 < SEQ / 64) {
            LOAD_KV(buf ^ 1, (ti + 1) * 64);
        } else {
            asm volatile("cp.async.commit_group;\n");
        }
        asm volatile("cp.async.wait_group 1;\n");
        __syncthreads();

        const __half* Ks = Kb + buf * KVSTAGE;
        const __half* Vs = Vb + buf * KVSTAGE;

        float s[8][4];
        #pragma unroll
        for (int nt = 0; nt < 8; nt++)
            #pragma unroll
            for (int i = 0; i < 4; i++) s[nt][i] = 0.0f;

        #pragma unroll
        for (int kc = 0; kc < 4; kc++) {
            #pragma unroll
            for (int nt = 0; nt < 8; nt++) {
                unsigned b[2];
                b[0] = *reinterpret_cast<const unsigned*>(&Ks[(nt * 8 + g) * QSTR + kc * 16 + tig * 2]);
                b[1] = *reinterpret_cast<const unsigned*>(&Ks[(nt * 8 + g) * QSTR + kc * 16 + tig * 2 + 8]);
                mma16(s[nt], qa[kc], b);
            }
        }

        unsigned pa[8][2];
        #pragma unroll
        for (int nt = 0; nt < 8; nt++) {
            float cb0 = lccs[buf][nt * 8 + tig * 2];
            float cb1 = lccs[buf][nt * 8 + tig * 2 + 1];
            float v0 = s[nt][0] + rb0 + cb0;
            float v1 = s[nt][1] + rb0 + cb1;
            float v2 = s[nt][2] + rb1 + cb0;
            float v3 = s[nt][3] + rb1 + cb1;
            v0 = fminf(10.0f, fmaxf(-10.0f, v0));
            v1 = fminf(10.0f, fmaxf(-10.0f, v1));
            v2 = fminf(10.0f, fmaxf(-10.0f, v2));
            v3 = fminf(10.0f, fmaxf(-10.0f, v3));
            __half2 p01 = __floats2half2_rn(__expf(v0), __expf(v1));
            __half2 p23 = __floats2half2_rn(__expf(v2), __expf(v3));
            pa[nt][0] = h2u(p01);
            pa[nt][1] = h2u(p23);
            float2 f01 = __half22float2(p01);
            float2 f23 = __half22float2(p23);
            d0 += f01.x + f01.y;
            d1 += f23.x + f23.y;
        }

        #pragma unroll
        for (int kc = 0; kc < 4; kc++) {
            unsigned a[4];
            a[0] = pa[2 * kc][0];
            a[1] = pa[2 * kc][1];
            a[2] = pa[2 * kc + 1][0];
            a[3] = pa[2 * kc + 1][1];
            unsigned vb[8][2];
            #pragma unroll
            for (int ntp = 0; ntp < 4; ntp++) {
                unsigned t4[4];
                ldsm4t(t4, &Vs[(kc * 16 + (lt & 1) * 8 + li) * QSTR + (ntp * 2 + (lt >> 1)) * 8]);
                vb[2 * ntp][0]     = t4[0]; vb[2 * ntp][1]     = t4[1];
                vb[2 * ntp + 1][0] = t4[2]; vb[2 * ntp + 1][1] = t4[3];
            }
            #pragma unroll
            for (int nt = 0; nt < 8; nt++)
                mma16(o[nt], a, vb[nt]);
        }
    }
    #undef LOAD_KV

    d0 += __shfl_xor_sync(0xffffffffu, d0, 1);
    d0 += __shfl_xor_sync(0xffffffffu, d0, 2);
    d1 += __shfl_xor_sync(0xffffffffu, d1, 1);
    d1 += __shfl_xor_sync(0xffffffffu, d1, 2);
    const float inv0 = 1.0f / d0;
    const float inv1 = 1.0f / d1;

    const int r0 = m0 + warp * 16 + g;
    const int r1 = r0 + 8;
    #pragma unroll
    for (int nt = 0; nt < 8; nt++) {
        const int c = h * HD + nt * 8 + tig * 2;
        *reinterpret_cast<unsigned*>(out + (size_t)r0 * DM + c) =
            h2u(__floats2half2_rn(o[nt][0] * inv0, o[nt][1] * inv0));
        *reinterpret_cast<unsigned*>(out + (size_t)r1 * DM + c) =
            h2u(__floats2half2_rn(o[nt][2] * inv1, o[nt][3] * inv1));
    }
}

// ---------------- launch --------------------------------------------------------
extern "C" void kernel_launch(void* const* d_in, const int* in_sizes, int n_in,
                              void* d_out, int out_size)
{
    const float* x     = (const float*)d_in[0];
    const float* lcc   = (const float*)d_in[1];
    const float* w_qkv = (const float*)d_in[2];
    const float* b_qkv = (const float*)d_in[3];
    const float* w_out = (const float*)d_in[4];
    const float* b_out = (const float*)d_in[5];
    const float* ln1_g = (const float*)d_in[6];
    const float* ln1_b = (const float*)d_in[7];
    const float* ln2_g = (const float*)d_in[8];
    const float* ln2_b = (const float*)d_in[9];
    const float* w_ff1 = (const float*)d_in[10];
    const float* b_ff1 = (const float*)d_in[11];
    const float* w_ff2 = (const float*)d_in[12];
    const float* b_ff2 = (const float*)d_in[13];
    float* out = (float*)d_out;

    __half *normed, *q, *k, *v, *attn, *normed2, *ffh;
    __half *wqkv_h, *wout_h, *wff1_h, *wff2_h;
    float *x2;
    cudaGetSymbolAddress((void**)&normed,  g_normed);
    cudaGetSymbolAddress((void**)&q,       g_q);
    cudaGetSymbolAddress((void**)&k,       g_k);
    cudaGetSymbolAddress((void**)&v,       g_v);
    cudaGetSymbolAddress((void**)&attn,    g_attn);
    cudaGetSymbolAddress((void**)&x2,      g_x2);
    cudaGetSymbolAddress((void**)&normed2, g_normed2);
    cudaGetSymbolAddress((void**)&ffh,     g_ffh);
    cudaGetSymbolAddress((void**)&wqkv_h,  g_wqkv_h);
    cudaGetSymbolAddress((void**)&wout_h,  g_wout_h);
    cudaGetSymbolAddress((void**)&wff1_h,  g_wff1_h);
    cudaGetSymbolAddress((void**)&wff2_h,  g_wff2_h);

    const int smem = GNST * STAGE_H * 2;
    cudaFuncSetAttribute(hgemm<1>, cudaFuncAttributeMaxDynamicSharedMemorySize, smem);
    cudaFuncSetAttribute(hgemm<2>, cudaFuncAttributeMaxDynamicSharedMemorySize, smem);
    cudaFuncSetAttribute(hgemm<3>, cudaFuncAttributeMaxDynamicSharedMemorySize, smem);

    const int asmem = (128 * QSTR + 4 * KVSTAGE) * 2;
    cudaFuncSetAttribute(attn_h_kernel, cudaFuncAttributeMaxDynamicSharedMemorySize, asmem);

    // 0. convert all weights to fp16 (single launch)
    cvt_all_kernel<<<296, 256>>>(
        w_qkv, wqkv_h, DM * 3 * DM / 4,
        w_out, wout_h, DM * DM / 4,
        w_ff1, wff1_h, DM * DFF / 4,
        w_ff2, wff2_h, DFF * DM / 4);

    // 1. LN1 (fp16 output)
    ln_kernel<<<SEQ, 256>>>(x, ln1_g, ln1_b, normed);
    // 2. QKV projection + fused split/cosine-normalize/relayout
    hgemm<3><<<dim3(SEQ / 128, 3 * DM / 128), 256, smem>>>(
        normed, wqkv_h, b_qkv, nullptr, nullptr, q, k, v, SEQ, 3 * DM, DM);
    // 3. attention (fp16 MMA, pipelined K/V)
    attn_h_kernel<<<dim3(SEQ / 128, NH), 256, asmem>>>(q, k, v, lcc, attn);
    // 4. out projection + residual (fp32 out)
    hgemm<1><<<dim3(SEQ / 128, DM / 128), 256, smem>>>(
        attn, wout_h, b_out, x, x2, nullptr, nullptr, nullptr, SEQ, DM, DM);
    // 5. LN2 (fp16 output)
    ln_kernel<<<SEQ, 256>>>(x2, ln2_g, ln2_b, normed2);
    // 6. FF1 + exact GELU (fp16 output)
    hgemm<2><<<dim3(SEQ / 128, DFF / 128), 256, smem>>>(
        normed2, wff1_h, b_ff1, nullptr, ffh, nullptr, nullptr, nullptr, SEQ, DFF, DM);
    // 7. FF2 + residual -> out (fp32)
    hgemm<1><<<dim3(SEQ / 128, DM / 128), 256, smem>>>(
        ffh, wff2_h, b_ff2, x2, out, nullptr, nullptr, nullptr, SEQ, DM, DFF);
}

// round 11
// speedup vs baseline: 2.3167x; 1.0355x over previous
#include <cuda_runtime.h>
#include <cuda_fp16.h>
#include <cstdint>
#include <math.h>

#define SEQ  2048
#define DM   1024
#define NH   16
#define HD   64
#define DFF  4096

// ---------------- scratch (no allocation allowed) ----------------
__device__ __half g_normed [SEQ * DM];
__device__ __half g_q      [NH * SEQ * HD];
__device__ __half g_k      [NH * SEQ * HD];
__device__ __half g_v      [NH * SEQ * HD];
__device__ __half g_attn   [SEQ * DM];
__device__ float  g_x2     [SEQ * DM];
__device__ __half g_normed2[SEQ * DM];
__device__ __half g_ffh    [SEQ * DFF];
// fp16 weight copies
__device__ __half g_wqkv_h [DM * 3 * DM];
__device__ __half g_wout_h [DM * DM];
__device__ __half g_wff1_h [DM * DFF];
__device__ __half g_wff2_h [DFF * DM];

// ---------------- helpers ----------------
__device__ __forceinline__ unsigned h2u(__half2 h) { return *reinterpret_cast<unsigned*>(&h); }

__device__ __forceinline__ void mma16(float* d, const unsigned* a, const unsigned* b) {
    asm volatile(
        "mma.sync.aligned.m16n8k16.row.col.f32.f16.f16.f32 "
        "{%0,%1,%2,%3}, {%4,%5,%6,%7}, {%8,%9}, {%0,%1,%2,%3};\n"
        : "+f"(d[0]), "+f"(d[1]), "+f"(d[2]), "+f"(d[3])
        : "r"(a[0]), "r"(a[1]), "r"(a[2]), "r"(a[3]), "r"(b[0]), "r"(b[1]));
}
__device__ __forceinline__ void cp16(void* sdst, const void* gsrc) {
    unsigned int d = (unsigned int)__cvta_generic_to_shared(sdst);
    asm volatile("cp.async.cg.shared.global [%0], [%1], 16;\n" :: "r"(d), "l"(gsrc));
}
__device__ __forceinline__ void ldsm4(unsigned* r, const void* saddr) {
    unsigned int ad = (unsigned int)__cvta_generic_to_shared(saddr);
    asm volatile("ldmatrix.sync.aligned.m8n8.x4.shared.b16 {%0,%1,%2,%3}, [%4];\n"
        : "=r"(r[0]), "=r"(r[1]), "=r"(r[2]), "=r"(r[3]) : "r"(ad));
}
__device__ __forceinline__ void ldsm4t(unsigned* r, const void* saddr) {
    unsigned int ad = (unsigned int)__cvta_generic_to_shared(saddr);
    asm volatile("ldmatrix.sync.aligned.m8n8.x4.trans.shared.b16 {%0,%1,%2,%3}, [%4];\n"
        : "=r"(r[0]), "=r"(r[1]), "=r"(r[2]), "=r"(r[3]) : "r"(ad));
}

// ---------------- fused weight fp32 -> fp16 convert ----------------
__global__ __launch_bounds__(256) void cvt_all_kernel(
    const float* __restrict__ s0, __half* __restrict__ d0, int n0,
    const float* __restrict__ s1, __half* __restrict__ d1, int n1,
    const float* __restrict__ s2, __half* __restrict__ d2, int n2,
    const float* __restrict__ s3, __half* __restrict__ d3, int n3)
{
    int i = blockIdx.x * blockDim.x + threadIdx.x;
    int stride = gridDim.x * blockDim.x;
    #define CVT_LOOP(S, D, N) \
    for (int j = i; j < N; j += stride) { \
        float4 v = reinterpret_cast<const float4*>(S)[j]; \
        __half2 lo = __floats2half2_rn(v.x, v.y); \
        __half2 hi = __floats2half2_rn(v.z, v.w); \
        reinterpret_cast<uint2*>(D)[j] = make_uint2(h2u(lo), h2u(hi)); \
    }
    CVT_LOOP(s0, d0, n0) CVT_LOOP(s1, d1, n1) CVT_LOOP(s2, d2, n2) CVT_LOOP(s3, d3, n3)
    #undef CVT_LOOP
}

// ---------------- LayerNorm (fp16 output: feeds GEMM A) ----------------
__global__ __launch_bounds__(256) void ln_kernel(
    const float* __restrict__ x, const float* __restrict__ g,
    const float* __restrict__ b, __half* __restrict__ out)
{
    int row = blockIdx.x;
    int tid = threadIdx.x;
    const float* xr = x + (size_t)row * DM;
    float4 xv = reinterpret_cast<const float4*>(xr)[tid];
    float s  = xv.x + xv.y + xv.z + xv.w;
    float sq = xv.x*xv.x + xv.y*xv.y + xv.z*xv.z + xv.w*xv.w;

    __shared__ float sh1[256], sh2[256];
    sh1[tid] = s; sh2[tid] = sq;
    __syncthreads();
    #pragma unroll
    for (int o = 128; o > 0; o >>= 1) {
        if (tid < o) { sh1[tid] += sh1[tid + o]; sh2[tid] += sh2[tid + o]; }
        __syncthreads();
    }
    float mu   = sh1[0] * (1.0f / DM);
    float var  = sh2[0] * (1.0f / DM) - mu * mu;
    float rstd = rsqrtf(var + 1e-5f);

    float4 gv = reinterpret_cast<const float4*>(g)[tid];
    float4 bv = reinterpret_cast<const float4*>(b)[tid];
    __half2 lo = __floats2half2_rn((xv.x - mu) * rstd * gv.x + bv.x,
                                   (xv.y - mu) * rstd * gv.y + bv.y);
    __half2 hi = __floats2half2_rn((xv.z - mu) * rstd * gv.z + bv.z,
                                   (xv.w - mu) * rstd * gv.w + bv.w);
    reinterpret_cast<uint2*>(out + (size_t)row * DM)[tid] = make_uint2(h2u(lo), h2u(hi));
}

// ---------------- fp16 MMA GEMM: 128x128 block, 8 warps (4x2), BK=32 ---------
// OP = 1: float C = A*B + bias + res (fp32 residual)
// OP = 2: half C = gelu(A*B + bias)
// OP = 3: QKV epilogue — per-(row,head) L2-normalize q,k; write [H,L,64] layout
#define ASTR 40
#define BSTR 136
#define HBK  32
#define STAGE_H (128 * ASTR + HBK * BSTR)
#define GNST 3

template<int OP>
__global__ __launch_bounds__(256) void hgemm(
    const __half* __restrict__ A, const __half* __restrict__ B,
    const float* __restrict__ bias, const float* __restrict__ res,
    void* __restrict__ Cv, __half* __restrict__ Qo, __half* __restrict__ Ko,
    __half* __restrict__ Vo, int M, int N, int K)
{
    extern __shared__ __half sh[];

    const int tid  = threadIdx.x;
    const int lane = tid & 31;
    const int warp = tid >> 5;
    const int g    = lane >> 2;
    const int tig  = lane & 3;
    const int wm   = warp >> 1;
    const int wn   = warp & 1;
    const int m0   = blockIdx.x * 128;
    const int n0   = blockIdx.y * 128;

    const int lt = lane >> 3;
    const int li = lane & 7;
    const int arow_l = wm * 32 + (lt & 1) * 8 + li;
    const int acol_l = (lt >> 1) * 8;
    const int brow_l = (lt & 1) * 8 + li;
    const int bcol_l = wn * 64 + (lt >> 1) * 8;

    float acc[2][8][4];
    #pragma unroll
    for (int mt = 0; mt < 2; mt++)
        #pragma unroll
        for (int nt = 0; nt < 8; nt++)
            #pragma unroll
            for (int i = 0; i < 4; i++) acc[mt][nt][i] = 0.0f;

    const int nsteps = K >> 5;

    #pragma unroll
    for (int s = 0; s < GNST - 1; s++) {
        __half* As = sh + s * STAGE_H;
        __half* Bs = As + 128 * ASTR;
        #pragma unroll
        for (int t = 0; t < 2; t++) {
            int idx = t * 256 + tid;
            int arw = idx >> 2, aof = (idx & 3) * 8;
            cp16(&As[arw * ASTR + aof], A + (size_t)(m0 + arw) * K + s * HBK + aof);
            int brw = idx >> 4, bof = (idx & 15) * 8;
            cp16(&Bs[brw * BSTR + bof], B + (size_t)(s * HBK + brw) * N + n0 + bof);
        }
        asm volatile("cp.async.commit_group;\n");
    }

    for (int it = 0; it < nsteps; it++) {
        asm volatile("cp.async.wait_group %0;\n" :: "n"(GNST - 2));
        __syncthreads();

        if (it + GNST - 1 < nsteps) {
            const int s  = (it + GNST - 1) % GNST;
            const int kt = (it + GNST - 1) * HBK;
            __half* As = sh + s * STAGE_H;
            __half* Bs = As + 128 * ASTR;
            #pragma unroll
            for (int t = 0; t < 2; t++) {
                int idx = t * 256 + tid;
                int arw = idx >> 2, aof = (idx & 3) * 8;
                cp16(&As[arw * ASTR + aof], A + (size_t)(m0 + arw) * K + kt + aof);
                int brw = idx >> 4, bof = (idx & 15) * 8;
                cp16(&Bs[brw * BSTR + bof], B + (size_t)(kt + brw) * N + n0 + bof);
            }
        }
        asm volatile("cp.async.commit_group;\n");

        const __half* As = sh + (it % GNST) * STAGE_H;
        const __half* Bs = As + 128 * ASTR;

        #pragma unroll
        for (int kb = 0; kb < HBK; kb += 16) {
            unsigned a[2][4], b[8][2];
            ldsm4(a[0], &As[arow_l * ASTR + kb + acol_l]);
            ldsm4(a[1], &As[(arow_l + 16) * ASTR + kb + acol_l]);
            #pragma unroll
            for (int ntp = 0; ntp < 4; ntp++) {
                unsigned t4[4];
                ldsm4t(t4, &Bs[(kb + brow_l) * BSTR + bcol_l + ntp * 16]);
                b[2 * ntp][0]     = t4[0]; b[2 * ntp][1]     = t4[1];
                b[2 * ntp + 1][0] = t4[2]; b[2 * ntp + 1][1] = t4[3];
            }
            #pragma unroll
            for (int mt = 0; mt < 2; mt++)
                #pragma unroll
                for (int nt = 0; nt < 8; nt++)
                    mma16(acc[mt][nt], a[mt], b[nt]);
        }
    }

    // ---------------- epilogue ----------------
    if (OP == 3) {
        const int grp = (n0 >> 6) + wn;     // 0..47
        const int cls = grp >> 4;           // 0=q, 1=k, 2=v
        const int hh  = grp & 15;
        __half* Dst = (cls == 0) ? Qo : (cls == 1) ? Ko : Vo;

        #pragma unroll
        for (int mt = 0; mt < 2; mt++) {
            const int r0 = m0 + wm * 32 + mt * 16 + g;
            const int r1 = r0 + 8;
            float v[8][4];
            float ss0 = 0.0f, ss1 = 0.0f;
            #pragma unroll
            for (int nt = 0; nt < 8; nt++) {
                const int c = n0 + wn * 64 + nt * 8 + tig * 2;
                const float b0 = bias[c], b1 = bias[c + 1];
                v[nt][0] = acc[mt][nt][0] + b0;
                v[nt][1] = acc[mt][nt][1] + b1;
                v[nt][2] = acc[mt][nt][2] + b0;
                v[nt][3] = acc[mt][nt][3] + b1;
                ss0 += v[nt][0] * v[nt][0] + v[nt][1] * v[nt][1];
                ss1 += v[nt][2] * v[nt][2] + v[nt][3] * v[nt][3];
            }
            ss0 += __shfl_xor_sync(0xffffffffu, ss0, 1);
            ss0 += __shfl_xor_sync(0xffffffffu, ss0, 2);
            ss1 += __shfl_xor_sync(0xffffffffu, ss1, 1);
            ss1 += __shfl_xor_sync(0xffffffffu, ss1, 2);
            float sc0 = 1.0f, sc1 = 1.0f;
            if (cls == 0) {
                sc0 = 0.125f / fmaxf(sqrtf(ss0), 1e-12f);
                sc1 = 0.125f / fmaxf(sqrtf(ss1), 1e-12f);
            } else if (cls == 1) {
                sc0 = 1.0f / fmaxf(sqrtf(ss0), 1e-12f);
                sc1 = 1.0f / fmaxf(sqrtf(ss1), 1e-12f);
            }
            __half* d0p = Dst + ((size_t)hh * SEQ + r0) * HD + tig * 2;
            __half* d1p = Dst + ((size_t)hh * SEQ + r1) * HD + tig * 2;
            #pragma unroll
            for (int nt = 0; nt < 8; nt++) {
                *reinterpret_cast<unsigned*>(d0p + nt * 8) =
                    h2u(__floats2half2_rn(v[nt][0] * sc0, v[nt][1] * sc0));
                *reinterpret_cast<unsigned*>(d1p + nt * 8) =
                    h2u(__floats2half2_rn(v[nt][2] * sc1, v[nt][3] * sc1));
            }
        }
        return;
    }

    #pragma unroll
    for (int mt = 0; mt < 2; mt++) {
        const int r0 = m0 + wm * 32 + mt * 16 + g;
        const int r1 = r0 + 8;
        #pragma unroll
        for (int nt = 0; nt < 8; nt++) {
            const int c = n0 + wn * 64 + nt * 8 + tig * 2;
            const float b0 = bias[c], b1 = bias[c + 1];
            float v0 = acc[mt][nt][0] + b0;
            float v1 = acc[mt][nt][1] + b1;
            float v2 = acc[mt][nt][2] + b0;
            float v3 = acc[mt][nt][3] + b1;
            if (OP == 1) {
                float* Cf = (float*)Cv;
                const float2 ra = *reinterpret_cast<const float2*>(res + (size_t)r0 * N + c);
                const float2 rb = *reinterpret_cast<const float2*>(res + (size_t)r1 * N + c);
                *reinterpret_cast<float2*>(Cf + (size_t)r0 * N + c) = make_float2(v0 + ra.x, v1 + ra.y);
                *reinterpret_cast<float2*>(Cf + (size_t)r1 * N + c) = make_float2(v2 + rb.x, v3 + rb.y);
            } else {
                if (OP == 2) {
                    v0 = 0.5f * v0 * (1.0f + erff(v0 * 0.70710678118654752f));
                    v1 = 0.5f * v1 * (1.0f + erff(v1 * 0.70710678118654752f));
                    v2 = 0.5f * v2 * (1.0f + erff(v2 * 0.70710678118654752f));
                    v3 = 0.5f * v3 * (1.0f + erff(v3 * 0.70710678118654752f));
                }
                __half* Ch = (__half*)Cv;
                *reinterpret_cast<unsigned*>(Ch + (size_t)r0 * N + c) = h2u(__floats2half2_rn(v0, v1));
                *reinterpret_cast<unsigned*>(Ch + (size_t)r1 * N + c) = h2u(__floats2half2_rn(v2, v3));
            }
        }
    }
}

// ---------------- fp16 MMA attention, double-buffered cp.async K/V ------------
// Scores bounded: |s|<=0.125, bias in [0,0.1] => clip at +-10 is dead code.
// Row bias exp factor cancels in softmax; column factor E_c folded as multiply.
// K b-fragments via non-trans ldmatrix.x4 (B[n][k] storage == b-frag layout).
#define QSTR 72
#define KVSTAGE (64 * QSTR)
__global__ __launch_bounds__(256) void attn_h_kernel(
    const __half* __restrict__ Q, const __half* __restrict__ Km,
    const __half* __restrict__ V, const float* __restrict__ lcc,
    __half* __restrict__ out)
{
    extern __shared__ __half apool[];
    __half* Qs = apool;
    __half* Kb = apool + 128 * QSTR;
    __half* Vb = Kb + 2 * KVSTAGE;
    __shared__ float lccs[2][64];   // holds exp(lcc*0.05) per key

    const int h    = blockIdx.y;
    const int m0   = blockIdx.x * 128;
    const int tid  = threadIdx.x;
    const int lane = tid & 31;
    const int warp = tid >> 5;
    const int g    = lane >> 2;
    const int tig  = lane & 3;
    const int lt   = lane >> 3;
    const int li   = lane & 7;

    // K b-frag ldmatrix lane address components:
    // tile t = lane/8: (n-half = t>>1, k-half = t&1); row within = lane&7
    const int kb_n = ((lane >> 4) << 3) + li;   // 0..15
    const int kb_k = ((lane >> 3) & 1) * 8;     // 0 or 8

    const __half* Kg = Km + (size_t)h * SEQ * HD;
    const __half* Vg = V  + (size_t)h * SEQ * HD;

    #define LOAD_KV(sb, kt) do { \
        __half* Kd = Kb + (sb) * KVSTAGE; \
        __half* Vd = Vb + (sb) * KVSTAGE; \
        _Pragma("unroll") \
        for (int t = 0; t < 2; t++) { \
            int idx = t * 256 + tid; \
            int row = idx >> 3; \
            int off = (idx & 7) * 8; \
            cp16(&Kd[row * QSTR + off], Kg + (size_t)((kt) + row) * HD + off); \
            cp16(&Vd[row * QSTR + off], Vg + (size_t)((kt) + row) * HD + off); \
        } \
        asm volatile("cp.async.commit_group;\n"); \
        if (tid < 64) lccs[sb][tid] = __expf(lcc[(kt) + tid] * 0.05f); \
    } while (0)

    LOAD_KV(0, 0);

    {
        const __half* Qg = Q + ((size_t)h * SEQ + m0) * HD;
        #pragma unroll
        for (int t = 0; t < 4; t++) {
            int idx = t * 256 + tid;
            int row = idx >> 3;
            int off = (idx & 7) * 8;
            *reinterpret_cast<uint4*>(&Qs[row * QSTR + off]) =
                *reinterpret_cast<const uint4*>(Qg + (size_t)row * HD + off);
        }
    }
    __syncthreads();

    unsigned qa[4][4];
    {
        const int qrow = warp * 16 + (lt & 1) * 8 + li;
        const int qcol = (lt >> 1) * 8;
        #pragma unroll
        for (int kc = 0; kc < 4; kc++)
            ldsm4(qa[kc], &Qs[qrow * QSTR + kc * 16 + qcol]);
    }

    float o[8][4];
    #pragma unroll
    for (int nt = 0; nt < 8; nt++)
        #pragma unroll
        for (int i = 0; i < 4; i++) o[nt][i] = 0.0f;
    float d0 = 0.0f, d1 = 0.0f;

    for (int ti = 0; ti < SEQ / 64; ti++) {
        const int buf = ti & 1;
        __syncthreads();
        if (ti + 1 < SEQ / 64) {
            LOAD_KV(buf ^ 1, (ti + 1) * 64);
        } else {
            asm volatile("cp.async.commit_group;\n");
        }
        asm volatile("cp.async.wait_group 1;\n");
        __syncthreads();

        const __half* Ks = Kb + buf * KVSTAGE;
        const __half* Vs = Vb + buf * KVSTAGE;

        // ---- S = Q @ K^T (b-frags via ldmatrix.x4) ----
        float s[8][4];
        #pragma unroll
        for (int nt = 0; nt < 8; nt++)
            #pragma unroll
            for (int i = 0; i < 4; i++) s[nt][i] = 0.0f;

        #pragma unroll
        for (int kc = 0; kc < 4; kc++) {
            #pragma unroll
            for (int ng = 0; ng < 4; ng++) {
                unsigned t4[4];
                ldsm4(t4, &Ks[(ng * 16 + kb_n) * QSTR + kc * 16 + kb_k]);
                mma16(s[2 * ng],     qa[kc], t4);
                mma16(s[2 * ng + 1], qa[kc], t4 + 2);
            }
        }

        // ---- softmax numerators: p = exp(s) * E_c (rb cancels; no clip) ----
        unsigned pa[8][2];
        #pragma unroll
        for (int nt = 0; nt < 8; nt++) {
            float ec0 = lccs[buf][nt * 8 + tig * 2];
            float ec1 = lccs[buf][nt * 8 + tig * 2 + 1];
            float p0 = __expf(s[nt][0]) * ec0;
            float p1 = __expf(s[nt][1]) * ec1;
            float p2 = __expf(s[nt][2]) * ec0;
            float p3 = __expf(s[nt][3]) * ec1;
            __half2 p01 = __floats2half2_rn(p0, p1);
            __half2 p23 = __floats2half2_rn(p2, p3);
            pa[nt][0] = h2u(p01);
            pa[nt][1] = h2u(p23);
            float2 f01 = __half22float2(p01);
            float2 f23 = __half22float2(p23);
            d0 += f01.x + f01.y;
            d1 += f23.x + f23.y;
        }

        // ---- O += P @ V ----
        #pragma unroll
        for (int kc = 0; kc < 4; kc++) {
            unsigned a[4];
            a[0] = pa[2 * kc][0];
            a[1] = pa[2 * kc][1];
            a[2] = pa[2 * kc + 1][0];
            a[3] = pa[2 * kc + 1][1];
            unsigned vb[8][2];
            #pragma unroll
            for (int ntp = 0; ntp < 4; ntp++) {
                unsigned t4[4];
                ldsm4t(t4, &Vs[(kc * 16 + (lt & 1) * 8 + li) * QSTR + (ntp * 2 + (lt >> 1)) * 8]);
                vb[2 * ntp][0]     = t4[0]; vb[2 * ntp][1]     = t4[1];
                vb[2 * ntp + 1][0] = t4[2]; vb[2 * ntp + 1][1] = t4[3];
            }
            #pragma unroll
            for (int nt = 0; nt < 8; nt++)
                mma16(o[nt], a, vb[nt]);
        }
    }
    #undef LOAD_KV

    d0 += __shfl_xor_sync(0xffffffffu, d0, 1);
    d0 += __shfl_xor_sync(0xffffffffu, d0, 2);
    d1 += __shfl_xor_sync(0xffffffffu, d1, 1);
    d1 += __shfl_xor_sync(0xffffffffu, d1, 2);
    const float inv0 = 1.0f / d0;
    const float inv1 = 1.0f / d1;

    const int r0 = m0 + warp * 16 + g;
    const int r1 = r0 + 8;
    #pragma unroll
    for (int nt = 0; nt < 8; nt++) {
        const int c = h * HD + nt * 8 + tig * 2;
        *reinterpret_cast<unsigned*>(out + (size_t)r0 * DM + c) =
            h2u(__floats2half2_rn(o[nt][0] * inv0, o[nt][1] * inv0));
        *reinterpret_cast<unsigned*>(out + (size_t)r1 * DM + c) =
            h2u(__floats2half2_rn(o[nt][2] * inv1, o[nt][3] * inv1));
    }
}

// ---------------- launch --------------------------------------------------------
extern "C" void kernel_launch(void* const* d_in, const int* in_sizes, int n_in,
                              void* d_out, int out_size)
{
    const float* x     = (const float*)d_in[0];
    const float* lcc   = (const float*)d_in[1];
    const float* w_qkv = (const float*)d_in[2];
    const float* b_qkv = (const float*)d_in[3];
    const float* w_out = (const float*)d_in[4];
    const float* b_out = (const float*)d_in[5];
    const float* ln1_g = (const float*)d_in[6];
    const float* ln1_b = (const float*)d_in[7];
    const float* ln2_g = (const float*)d_in[8];
    const float* ln2_b = (const float*)d_in[9];
    const float* w_ff1 = (const float*)d_in[10];
    const float* b_ff1 = (const float*)d_in[11];
    const float* w_ff2 = (const float*)d_in[12];
    const float* b_ff2 = (const float*)d_in[13];
    float* out = (float*)d_out;

    __half *normed, *q, *k, *v, *attn, *normed2, *ffh;
    __half *wqkv_h, *wout_h, *wff1_h, *wff2_h;
    float *x2;
    cudaGetSymbolAddress((void**)&normed,  g_normed);
    cudaGetSymbolAddress((void**)&q,       g_q);
    cudaGetSymbolAddress((void**)&k,       g_k);
    cudaGetSymbolAddress((void**)&v,       g_v);
    cudaGetSymbolAddress((void**)&attn,    g_attn);
    cudaGetSymbolAddress((void**)&x2,      g_x2);
    cudaGetSymbolAddress((void**)&normed2, g_normed2);
    cudaGetSymbolAddress((void**)&ffh,     g_ffh);
    cudaGetSymbolAddress((void**)&wqkv_h,  g_wqkv_h);
    cudaGetSymbolAddress((void**)&wout_h,  g_wout_h);
    cudaGetSymbolAddress((void**)&wff1_h,  g_wff1_h);
    cudaGetSymbolAddress((void**)&wff2_h,  g_wff2_h);

    const int smem = GNST * STAGE_H * 2;
    cudaFuncSetAttribute(hgemm<1>, cudaFuncAttributeMaxDynamicSharedMemorySize, smem);
    cudaFuncSetAttribute(hgemm<2>, cudaFuncAttributeMaxDynamicSharedMemorySize, smem);
    cudaFuncSetAttribute(hgemm<3>, cudaFuncAttributeMaxDynamicSharedMemorySize, smem);

    const int asmem = (128 * QSTR + 4 * KVSTAGE) * 2;
    cudaFuncSetAttribute(attn_h_kernel, cudaFuncAttributeMaxDynamicSharedMemorySize, asmem);

    // 0. convert all weights to fp16 (single launch)
    cvt_all_kernel<<<296, 256>>>(
        w_qkv, wqkv_h, DM * 3 * DM / 4,
        w_out, wout_h, DM * DM / 4,
        w_ff1, wff1_h, DM * DFF / 4,
        w_ff2, wff2_h, DFF * DM / 4);

    // 1. LN1 (fp16 output)
    ln_kernel<<<SEQ, 256>>>(x, ln1_g, ln1_b, normed);
    // 2. QKV projection + fused split/cosine-normalize/relayout
    hgemm<3><<<dim3(SEQ / 128, 3 * DM / 128), 256, smem>>>(
        normed, wqkv_h, b_qkv, nullptr, nullptr, q, k, v, SEQ, 3 * DM, DM);
    // 3. attention (fp16 MMA, pipelined K/V)
    attn_h_kernel<<<dim3(SEQ / 128, NH), 256, asmem>>>(q, k, v, lcc, attn);
    // 4. out projection + residual (fp32 out)
    hgemm<1><<<dim3(SEQ / 128, DM / 128), 256, smem>>>(
        attn, wout_h, b_out, x, x2, nullptr, nullptr, nullptr, SEQ, DM, DM);
    // 5. LN2 (fp16 output)
    ln_kernel<<<SEQ, 256>>>(x2, ln2_g, ln2_b, normed2);
    // 6. FF1 + exact GELU (fp16 output)
    hgemm<2><<<dim3(SEQ / 128, DFF / 128), 256, smem>>>(
        normed2, wff1_h, b_ff1, nullptr, ffh, nullptr, nullptr, nullptr, SEQ, DFF, DM);
    // 7. FF2 + residual -> out (fp32)
    hgemm<1><<<dim3(SEQ / 128, DM / 128), 256, smem>>>(
        ffh, wff2_h, b_ff2, x2, out, nullptr, nullptr, nullptr, SEQ, DM, DFF);
}

// round 12
// speedup vs baseline: 2.3667x; 1.0216x over previous
#include <cuda_runtime.h>
#include <cuda_fp16.h>
#include <cstdint>
#include <math.h>

#define SEQ  2048
#define DM   1024
#define NH   16
#define HD   64
#define DFF  4096

// ---------------- scratch (no allocation allowed) ----------------
__device__ __half g_normed [SEQ * DM];
__device__ __half g_q      [NH * SEQ * HD];
__device__ __half g_k      [NH * SEQ * HD];
__device__ __half g_v      [NH * SEQ * HD];
__device__ __half g_attn   [SEQ * DM];
__device__ float  g_x2     [SEQ * DM];
__device__ __half g_normed2[SEQ * DM];
__device__ __half g_ffh    [SEQ * DFF];
// fp16 weight copies
__device__ __half g_wqkv_h [DM * 3 * DM];
__device__ __half g_wout_h [DM * DM];
__device__ __half g_wff1_h [DM * DFF];
__device__ __half g_wff2_h [DFF * DM];

// ---------------- helpers ----------------
__device__ __forceinline__ unsigned h2u(__half2 h) { return *reinterpret_cast<unsigned*>(&h); }

__device__ __forceinline__ void mma16(float* d, const unsigned* a, const unsigned* b) {
    asm volatile(
        "mma.sync.aligned.m16n8k16.row.col.f32.f16.f16.f32 "
        "{%0,%1,%2,%3}, {%4,%5,%6,%7}, {%8,%9}, {%0,%1,%2,%3};\n"
        : "+f"(d[0]), "+f"(d[1]), "+f"(d[2]), "+f"(d[3])
        : "r"(a[0]), "r"(a[1]), "r"(a[2]), "r"(a[3]), "r"(b[0]), "r"(b[1]));
}
__device__ __forceinline__ void cp16(void* sdst, const void* gsrc) {
    unsigned int d = (unsigned int)__cvta_generic_to_shared(sdst);
    asm volatile("cp.async.cg.shared.global [%0], [%1], 16;\n" :: "r"(d), "l"(gsrc));
}
__device__ __forceinline__ void ldsm4(unsigned* r, const void* saddr) {
    unsigned int ad = (unsigned int)__cvta_generic_to_shared(saddr);
    asm volatile("ldmatrix.sync.aligned.m8n8.x4.shared.b16 {%0,%1,%2,%3}, [%4];\n"
        : "=r"(r[0]), "=r"(r[1]), "=r"(r[2]), "=r"(r[3]) : "r"(ad));
}
__device__ __forceinline__ void ldsm4t(unsigned* r, const void* saddr) {
    unsigned int ad = (unsigned int)__cvta_generic_to_shared(saddr);
    asm volatile("ldmatrix.sync.aligned.m8n8.x4.trans.shared.b16 {%0,%1,%2,%3}, [%4];\n"
        : "=r"(r[0]), "=r"(r[1]), "=r"(r[2]), "=r"(r[3]) : "r"(ad));
}

// ---------------- fused weight fp32 -> fp16 convert ----------------
__global__ __launch_bounds__(256) void cvt_all_kernel(
    const float* __restrict__ s0, __half* __restrict__ d0, int n0,
    const float* __restrict__ s1, __half* __restrict__ d1, int n1,
    const float* __restrict__ s2, __half* __restrict__ d2, int n2,
    const float* __restrict__ s3, __half* __restrict__ d3, int n3)
{
    int i = blockIdx.x * blockDim.x + threadIdx.x;
    int stride = gridDim.x * blockDim.x;
    #define CVT_LOOP(S, D, N) \
    for (int j = i; j < N; j += stride) { \
        float4 v = reinterpret_cast<const float4*>(S)[j]; \
        __half2 lo = __floats2half2_rn(v.x, v.y); \
        __half2 hi = __floats2half2_rn(v.z, v.w); \
        reinterpret_cast<uint2*>(D)[j] = make_uint2(h2u(lo), h2u(hi)); \
    }
    CVT_LOOP(s0, d0, n0) CVT_LOOP(s1, d1, n1) CVT_LOOP(s2, d2, n2) CVT_LOOP(s3, d3, n3)
    #undef CVT_LOOP
}

// ---------------- LayerNorm (fp16 output: feeds GEMM A) ----------------
__global__ __launch_bounds__(256) void ln_kernel(
    const float* __restrict__ x, const float* __restrict__ g,
    const float* __restrict__ b, __half* __restrict__ out)
{
    int row = blockIdx.x;
    int tid = threadIdx.x;
    const float* xr = x + (size_t)row * DM;
    float4 xv = reinterpret_cast<const float4*>(xr)[tid];
    float s  = xv.x + xv.y + xv.z + xv.w;
    float sq = xv.x*xv.x + xv.y*xv.y + xv.z*xv.z + xv.w*xv.w;

    __shared__ float sh1[256], sh2[256];
    sh1[tid] = s; sh2[tid] = sq;
    __syncthreads();
    #pragma unroll
    for (int o = 128; o > 0; o >>= 1) {
        if (tid < o) { sh1[tid] += sh1[tid + o]; sh2[tid] += sh2[tid + o]; }
        __syncthreads();
    }
    float mu   = sh1[0] * (1.0f / DM);
    float var  = sh2[0] * (1.0f / DM) - mu * mu;
    float rstd = rsqrtf(var + 1e-5f);

    float4 gv = reinterpret_cast<const float4*>(g)[tid];
    float4 bv = reinterpret_cast<const float4*>(b)[tid];
    __half2 lo = __floats2half2_rn((xv.x - mu) * rstd * gv.x + bv.x,
                                   (xv.y - mu) * rstd * gv.y + bv.y);
    __half2 hi = __floats2half2_rn((xv.z - mu) * rstd * gv.z + bv.z,
                                   (xv.w - mu) * rstd * gv.w + bv.w);
    reinterpret_cast<uint2*>(out + (size_t)row * DM)[tid] = make_uint2(h2u(lo), h2u(hi));
}

// ---------------- fp16 MMA GEMM: TM x 128 block, 8 warps, BK=32 --------------
// TM=128: warps 4x2 (tile 32x64); TM=64: warps 2x4 (tile 32x32) — better SM fill
// OP = 1: float C = A*B + bias + res (fp32 residual)
// OP = 2: half C = gelu(A*B + bias)
// OP = 3: QKV epilogue (TM=128 only) — L2-normalize q,k; write [H,L,64] layout
#define ASTR 40
#define BSTR 136
#define HBK  32
#define GNST 3

template<int TM, int OP>
__global__ __launch_bounds__(256) void hgemm(
    const __half* __restrict__ A, const __half* __restrict__ B,
    const float* __restrict__ bias, const float* __restrict__ res,
    void* __restrict__ Cv, __half* __restrict__ Qo, __half* __restrict__ Ko,
    __half* __restrict__ Vo, int M, int N, int K)
{
    constexpr int NWN   = (TM == 128) ? 2 : 4;   // warps along N
    constexpr int NT    = 16 / NWN;              // n-tiles (8-col) per warp
    constexpr int STAGE = TM * ASTR + HBK * BSTR;

    extern __shared__ __half sh[];

    const int tid  = threadIdx.x;
    const int lane = tid & 31;
    const int warp = tid >> 5;
    const int g    = lane >> 2;
    const int tig  = lane & 3;
    const int wm   = warp / NWN;
    const int wn   = warp % NWN;
    const int m0   = blockIdx.x * TM;
    const int n0   = blockIdx.y * 128;

    const int lt = lane >> 3;
    const int li = lane & 7;
    const int arow_l = wm * 32 + (lt & 1) * 8 + li;
    const int acol_l = (lt >> 1) * 8;
    const int brow_l = (lt & 1) * 8 + li;
    const int bcol_l = wn * (NT * 8) + (lt >> 1) * 8;

    float acc[2][NT][4];
    #pragma unroll
    for (int mt = 0; mt < 2; mt++)
        #pragma unroll
        for (int nt = 0; nt < NT; nt++)
            #pragma unroll
            for (int i = 0; i < 4; i++) acc[mt][nt][i] = 0.0f;

    const int nsteps = K >> 5;

    #define LOAD_STAGE(sp, kt) do { \
        __half* As = sh + (sp) * STAGE; \
        __half* Bs = As + TM * ASTR; \
        _Pragma("unroll") \
        for (int t = 0; t < TM / 64; t++) { \
            int idx = t * 256 + tid; \
            int arw = idx >> 2, aof = (idx & 3) * 8; \
            cp16(&As[arw * ASTR + aof], A + (size_t)(m0 + arw) * K + (kt) + aof); \
        } \
        _Pragma("unroll") \
        for (int t = 0; t < 2; t++) { \
            int idx = t * 256 + tid; \
            int brw = idx >> 4, bof = (idx & 15) * 8; \
            cp16(&Bs[brw * BSTR + bof], B + (size_t)((kt) + brw) * N + n0 + bof); \
        } \
        asm volatile("cp.async.commit_group;\n"); \
    } while (0)

    #pragma unroll
    for (int s = 0; s < GNST - 1; s++) LOAD_STAGE(s, s * HBK);

    for (int it = 0; it < nsteps; it++) {
        asm volatile("cp.async.wait_group %0;\n" :: "n"(GNST - 2));
        __syncthreads();

        if (it + GNST - 1 < nsteps)
            LOAD_STAGE((it + GNST - 1) % GNST, (it + GNST - 1) * HBK);
        else
            asm volatile("cp.async.commit_group;\n");

        const __half* As = sh + (it % GNST) * STAGE;
        const __half* Bs = As + TM * ASTR;

        #pragma unroll
        for (int kb = 0; kb < HBK; kb += 16) {
            unsigned a[2][4], b[NT][2];
            ldsm4(a[0], &As[arow_l * ASTR + kb + acol_l]);
            ldsm4(a[1], &As[(arow_l + 16) * ASTR + kb + acol_l]);
            #pragma unroll
            for (int ntp = 0; ntp < NT / 2; ntp++) {
                unsigned t4[4];
                ldsm4t(t4, &Bs[(kb + brow_l) * BSTR + bcol_l + ntp * 16]);
                b[2 * ntp][0]     = t4[0]; b[2 * ntp][1]     = t4[1];
                b[2 * ntp + 1][0] = t4[2]; b[2 * ntp + 1][1] = t4[3];
            }
            #pragma unroll
            for (int mt = 0; mt < 2; mt++)
                #pragma unroll
                for (int nt = 0; nt < NT; nt++)
                    mma16(acc[mt][nt], a[mt], b[nt]);
        }
    }
    #undef LOAD_STAGE

    // ---------------- epilogue ----------------
    if (OP == 3) {
        const int grp = (n0 >> 6) + wn;     // 0..47 (TM=128: wn in {0,1})
        const int cls = grp >> 4;           // 0=q, 1=k, 2=v
        const int hh  = grp & 15;
        __half* Dst = (cls == 0) ? Qo : (cls == 1) ? Ko : Vo;

        #pragma unroll
        for (int mt = 0; mt < 2; mt++) {
            const int r0 = m0 + wm * 32 + mt * 16 + g;
            const int r1 = r0 + 8;
            float v[NT][4];
            float ss0 = 0.0f, ss1 = 0.0f;
            #pragma unroll
            for (int nt = 0; nt < NT; nt++) {
                const int c = n0 + wn * (NT * 8) + nt * 8 + tig * 2;
                const float b0 = bias[c], b1 = bias[c + 1];
                v[nt][0] = acc[mt][nt][0] + b0;
                v[nt][1] = acc[mt][nt][1] + b1;
                v[nt][2] = acc[mt][nt][2] + b0;
                v[nt][3] = acc[mt][nt][3] + b1;
                ss0 += v[nt][0] * v[nt][0] + v[nt][1] * v[nt][1];
                ss1 += v[nt][2] * v[nt][2] + v[nt][3] * v[nt][3];
            }
            ss0 += __shfl_xor_sync(0xffffffffu, ss0, 1);
            ss0 += __shfl_xor_sync(0xffffffffu, ss0, 2);
            ss1 += __shfl_xor_sync(0xffffffffu, ss1, 1);
            ss1 += __shfl_xor_sync(0xffffffffu, ss1, 2);
            float sc0 = 1.0f, sc1 = 1.0f;
            if (cls == 0) {
                sc0 = 0.125f / fmaxf(sqrtf(ss0), 1e-12f);
                sc1 = 0.125f / fmaxf(sqrtf(ss1), 1e-12f);
            } else if (cls == 1) {
                sc0 = 1.0f / fmaxf(sqrtf(ss0), 1e-12f);
                sc1 = 1.0f / fmaxf(sqrtf(ss1), 1e-12f);
            }
            __half* d0p = Dst + ((size_t)hh * SEQ + r0) * HD + tig * 2;
            __half* d1p = Dst + ((size_t)hh * SEQ + r1) * HD + tig * 2;
            #pragma unroll
            for (int nt = 0; nt < NT; nt++) {
                *reinterpret_cast<unsigned*>(d0p + nt * 8) =
                    h2u(__floats2half2_rn(v[nt][0] * sc0, v[nt][1] * sc0));
                *reinterpret_cast<unsigned*>(d1p + nt * 8) =
                    h2u(__floats2half2_rn(v[nt][2] * sc1, v[nt][3] * sc1));
            }
        }
        return;
    }

    #pragma unroll
    for (int mt = 0; mt < 2; mt++) {
        const int r0 = m0 + wm * 32 + mt * 16 + g;
        const int r1 = r0 + 8;
        #pragma unroll
        for (int nt = 0; nt < NT; nt++) {
            const int c = n0 + wn * (NT * 8) + nt * 8 + tig * 2;
            const float b0 = bias[c], b1 = bias[c + 1];
            float v0 = acc[mt][nt][0] + b0;
            float v1 = acc[mt][nt][1] + b1;
            float v2 = acc[mt][nt][2] + b0;
            float v3 = acc[mt][nt][3] + b1;
            if (OP == 1) {
                float* Cf = (float*)Cv;
                const float2 ra = *reinterpret_cast<const float2*>(res + (size_t)r0 * N + c);
                const float2 rb = *reinterpret_cast<const float2*>(res + (size_t)r1 * N + c);
                *reinterpret_cast<float2*>(Cf + (size_t)r0 * N + c) = make_float2(v0 + ra.x, v1 + ra.y);
                *reinterpret_cast<float2*>(Cf + (size_t)r1 * N + c) = make_float2(v2 + rb.x, v3 + rb.y);
            } else {
                if (OP == 2) {
                    v0 = 0.5f * v0 * (1.0f + erff(v0 * 0.70710678118654752f));
                    v1 = 0.5f * v1 * (1.0f + erff(v1 * 0.70710678118654752f));
                    v2 = 0.5f * v2 * (1.0f + erff(v2 * 0.70710678118654752f));
                    v3 = 0.5f * v3 * (1.0f + erff(v3 * 0.70710678118654752f));
                }
                __half* Ch = (__half*)Cv;
                *reinterpret_cast<unsigned*>(Ch + (size_t)r0 * N + c) = h2u(__floats2half2_rn(v0, v1));
                *reinterpret_cast<unsigned*>(Ch + (size_t)r1 * N + c) = h2u(__floats2half2_rn(v2, v3));
            }
        }
    }
}

// ---------------- fp16 MMA attention, double-buffered cp.async K/V ------------
#define QSTR 72
#define KVSTAGE (64 * QSTR)
__global__ __launch_bounds__(256) void attn_h_kernel(
    const __half* __restrict__ Q, const __half* __restrict__ Km,
    const __half* __restrict__ V, const float* __restrict__ lcc,
    __half* __restrict__ out)
{
    extern __shared__ __half apool[];
    __half* Qs = apool;
    __half* Kb = apool + 128 * QSTR;
    __half* Vb = Kb + 2 * KVSTAGE;
    __shared__ float lccs[2][64];   // exp(lcc*0.05) per key

    const int h    = blockIdx.y;
    const int m0   = blockIdx.x * 128;
    const int tid  = threadIdx.x;
    const int lane = tid & 31;
    const int warp = tid >> 5;
    const int g    = lane >> 2;
    const int tig  = lane & 3;
    const int lt   = lane >> 3;
    const int li   = lane & 7;

    const int kb_n = ((lane >> 4) << 3) + li;
    const int kb_k = ((lane >> 3) & 1) * 8;

    const __half* Kg = Km + (size_t)h * SEQ * HD;
    const __half* Vg = V  + (size_t)h * SEQ * HD;

    #define LOAD_KV(sb, kt) do { \
        __half* Kd = Kb + (sb) * KVSTAGE; \
        __half* Vd = Vb + (sb) * KVSTAGE; \
        _Pragma("unroll") \
        for (int t = 0; t < 2; t++) { \
            int idx = t * 256 + tid; \
            int row = idx >> 3; \
            int off = (idx & 7) * 8; \
            cp16(&Kd[row * QSTR + off], Kg + (size_t)((kt) + row) * HD + off); \
            cp16(&Vd[row * QSTR + off], Vg + (size_t)((kt) + row) * HD + off); \
        } \
        asm volatile("cp.async.commit_group;\n"); \
        if (tid < 64) lccs[sb][tid] = __expf(lcc[(kt) + tid] * 0.05f); \
    } while (0)

    LOAD_KV(0, 0);

    {
        const __half* Qg = Q + ((size_t)h * SEQ + m0) * HD;
        #pragma unroll
        for (int t = 0; t < 4; t++) {
            int idx = t * 256 + tid;
            int row = idx >> 3;
            int off = (idx & 7) * 8;
            *reinterpret_cast<uint4*>(&Qs[row * QSTR + off]) =
                *reinterpret_cast<const uint4*>(Qg + (size_t)row * HD + off);
        }
    }
    __syncthreads();

    unsigned qa[4][4];
    {
        const int qrow = warp * 16 + (lt & 1) * 8 + li;
        const int qcol = (lt >> 1) * 8;
        #pragma unroll
        for (int kc = 0; kc < 4; kc++)
            ldsm4(qa[kc], &Qs[qrow * QSTR + kc * 16 + qcol]);
    }

    float o[8][4];
    #pragma unroll
    for (int nt = 0; nt < 8; nt++)
        #pragma unroll
        for (int i = 0; i < 4; i++) o[nt][i] = 0.0f;
    float d0 = 0.0f, d1 = 0.0f;

    for (int ti = 0; ti < SEQ / 64; ti++) {
        const int buf = ti & 1;
        __syncthreads();
        if (ti + 1 < SEQ / 64) {
            LOAD_KV(buf ^ 1, (ti + 1) * 64);
        } else {
            asm volatile("cp.async.commit_group;\n");
        }
        asm volatile("cp.async.wait_group 1;\n");
        __syncthreads();

        const __half* Ks = Kb + buf * KVSTAGE;
        const __half* Vs = Vb + buf * KVSTAGE;

        float s[8][4];
        #pragma unroll
        for (int nt = 0; nt < 8; nt++)
            #pragma unroll
            for (int i = 0; i < 4; i++) s[nt][i] = 0.0f;

        #pragma unroll
        for (int kc = 0; kc < 4; kc++) {
            #pragma unroll
            for (int ng = 0; ng < 4; ng++) {
                unsigned t4[4];
                ldsm4(t4, &Ks[(ng * 16 + kb_n) * QSTR + kc * 16 + kb_k]);
                mma16(s[2 * ng],     qa[kc], t4);
                mma16(s[2 * ng + 1], qa[kc], t4 + 2);
            }
        }

        // numerators p = exp(s)*E_c; denominator sums fp32 p's directly
        unsigned pa[8][2];
        #pragma unroll
        for (int nt = 0; nt < 8; nt++) {
            float ec0 = lccs[buf][nt * 8 + tig * 2];
            float ec1 = lccs[buf][nt * 8 + tig * 2 + 1];
            float p0 = __expf(s[nt][0]) * ec0;
            float p1 = __expf(s[nt][1]) * ec1;
            float p2 = __expf(s[nt][2]) * ec0;
            float p3 = __expf(s[nt][3]) * ec1;
            d0 += p0 + p1;
            d1 += p2 + p3;
            pa[nt][0] = h2u(__floats2half2_rn(p0, p1));
            pa[nt][1] = h2u(__floats2half2_rn(p2, p3));
        }

        #pragma unroll
        for (int kc = 0; kc < 4; kc++) {
            unsigned a[4];
            a[0] = pa[2 * kc][0];
            a[1] = pa[2 * kc][1];
            a[2] = pa[2 * kc + 1][0];
            a[3] = pa[2 * kc + 1][1];
            unsigned vb[8][2];
            #pragma unroll
            for (int ntp = 0; ntp < 4; ntp++) {
                unsigned t4[4];
                ldsm4t(t4, &Vs[(kc * 16 + (lt & 1) * 8 + li) * QSTR + (ntp * 2 + (lt >> 1)) * 8]);
                vb[2 * ntp][0]     = t4[0]; vb[2 * ntp][1]     = t4[1];
                vb[2 * ntp + 1][0] = t4[2]; vb[2 * ntp + 1][1] = t4[3];
            }
            #pragma unroll
            for (int nt = 0; nt < 8; nt++)
                mma16(o[nt], a, vb[nt]);
        }
    }
    #undef LOAD_KV

    d0 += __shfl_xor_sync(0xffffffffu, d0, 1);
    d0 += __shfl_xor_sync(0xffffffffu, d0, 2);
    d1 += __shfl_xor_sync(0xffffffffu, d1, 1);
    d1 += __shfl_xor_sync(0xffffffffu, d1, 2);
    const float inv0 = 1.0f / d0;
    const float inv1 = 1.0f / d1;

    const int r0 = m0 + warp * 16 + g;
    const int r1 = r0 + 8;
    #pragma unroll
    for (int nt = 0; nt < 8; nt++) {
        const int c = h * HD + nt * 8 + tig * 2;
        *reinterpret_cast<unsigned*>(out + (size_t)r0 * DM + c) =
            h2u(__floats2half2_rn(o[nt][0] * inv0, o[nt][1] * inv0));
        *reinterpret_cast<unsigned*>(out + (size_t)r1 * DM + c) =
            h2u(__floats2half2_rn(o[nt][2] * inv1, o[nt][3] * inv1));
    }
}

// ---------------- launch --------------------------------------------------------
extern "C" void kernel_launch(void* const* d_in, const int* in_sizes, int n_in,
                              void* d_out, int out_size)
{
    const float* x     = (const float*)d_in[0];
    const float* lcc   = (const float*)d_in[1];
    const float* w_qkv = (const float*)d_in[2];
    const float* b_qkv = (const float*)d_in[3];
    const float* w_out = (const float*)d_in[4];
    const float* b_out = (const float*)d_in[5];
    const float* ln1_g = (const float*)d_in[6];
    const float* ln1_b = (const float*)d_in[7];
    const float* ln2_g = (const float*)d_in[8];
    const float* ln2_b = (const float*)d_in[9];
    const float* w_ff1 = (const float*)d_in[10];
    const float* b_ff1 = (const float*)d_in[11];
    const float* w_ff2 = (const float*)d_in[12];
    const float* b_ff2 = (const float*)d_in[13];
    float* out = (float*)d_out;

    __half *normed, *q, *k, *v, *attn, *normed2, *ffh;
    __half *wqkv_h, *wout_h, *wff1_h, *wff2_h;
    float *x2;
    cudaGetSymbolAddress((void**)&normed,  g_normed);
    cudaGetSymbolAddress((void**)&q,       g_q);
    cudaGetSymbolAddress((void**)&k,       g_k);
    cudaGetSymbolAddress((void**)&v,       g_v);
    cudaGetSymbolAddress((void**)&attn,    g_attn);
    cudaGetSymbolAddress((void**)&x2,      g_x2);
    cudaGetSymbolAddress((void**)&normed2, g_normed2);
    cudaGetSymbolAddress((void**)&ffh,     g_ffh);
    cudaGetSymbolAddress((void**)&wqkv_h,  g_wqkv_h);
    cudaGetSymbolAddress((void**)&wout_h,  g_wout_h);
    cudaGetSymbolAddress((void**)&wff1_h,  g_wff1_h);
    cudaGetSymbolAddress((void**)&wff2_h,  g_wff2_h);

    const int smem128 = GNST * (128 * ASTR + HBK * BSTR) * 2;
    const int smem64  = GNST * (64 * ASTR + HBK * BSTR) * 2;
    cudaFuncSetAttribute((const void*)hgemm<128,3>, cudaFuncAttributeMaxDynamicSharedMemorySize, smem128);
    cudaFuncSetAttribute((const void*)hgemm<128,2>, cudaFuncAttributeMaxDynamicSharedMemorySize, smem128);
    cudaFuncSetAttribute((const void*)hgemm<64,1>,  cudaFuncAttributeMaxDynamicSharedMemorySize, smem64);

    const int asmem = (128 * QSTR + 4 * KVSTAGE) * 2;
    cudaFuncSetAttribute(attn_h_kernel, cudaFuncAttributeMaxDynamicSharedMemorySize, asmem);

    // 0. convert all weights to fp16 (single launch)
    cvt_all_kernel<<<296, 256>>>(
        w_qkv, wqkv_h, DM * 3 * DM / 4,
        w_out, wout_h, DM * DM / 4,
        w_ff1, wff1_h, DM * DFF / 4,
        w_ff2, wff2_h, DFF * DM / 4);

    // 1. LN1 (fp16 output)
    ln_kernel<<<SEQ, 256>>>(x, ln1_g, ln1_b, normed);
    // 2. QKV projection + fused split/cosine-normalize/relayout
    hgemm<128,3><<<dim3(SEQ / 128, 3 * DM / 128), 256, smem128>>>(
        normed, wqkv_h, b_qkv, nullptr, nullptr, q, k, v, SEQ, 3 * DM, DM);
    // 3. attention (fp16 MMA, pipelined K/V)
    attn_h_kernel<<<dim3(SEQ / 128, NH), 256, asmem>>>(q, k, v, lcc, attn);
    // 4. out projection + residual (fp32 out) — 64-row tiles for SM fill
    hgemm<64,1><<<dim3(SEQ / 64, DM / 128), 256, smem64>>>(
        attn, wout_h, b_out, x, x2, nullptr, nullptr, nullptr, SEQ, DM, DM);
    // 5. LN2 (fp16 output)
    ln_kernel<<<SEQ, 256>>>(x2, ln2_g, ln2_b, normed2);
    // 6. FF1 + exact GELU (fp16 output)
    hgemm<128,2><<<dim3(SEQ / 128, DFF / 128), 256, smem128>>>(
        normed2, wff1_h, b_ff1, nullptr, ffh, nullptr, nullptr, nullptr, SEQ, DFF, DM);
    // 7. FF2 + residual -> out (fp32) — 64-row tiles for SM fill
    hgemm<64,1><<<dim3(SEQ / 64, DM / 128), 256, smem64>>>(
        ffh, wff2_h, b_ff2, x2, out, nullptr, nullptr, nullptr, SEQ, DM, DFF);
}

// round 13
// speedup vs baseline: 2.3725x; 1.0025x over previous
#include <cuda_runtime.h>
#include <cuda_fp16.h>
#include <cstdint>
#include <math.h>

#define SEQ  2048
#define DM   1024
#define NH   16
#define HD   64
#define DFF  4096

// ---------------- scratch (no allocation allowed) ----------------
__device__ __half g_normed [SEQ * DM];
__device__ __half g_q      [NH * SEQ * HD];
__device__ __half g_k      [NH * SEQ * HD];
__device__ __half g_v      [NH * SEQ * HD];
__device__ __half g_attn   [SEQ * DM];
__device__ float  g_x2     [SEQ * DM];
__device__ __half g_normed2[SEQ * DM];
__device__ __half g_ffh    [SEQ * DFF];
// fp16 weight copies
__device__ __half g_wqkv_h [DM * 3 * DM];
__device__ __half g_wout_h [DM * DM];
__device__ __half g_wff1_h [DM * DFF];
__device__ __half g_wff2_h [DFF * DM];

// ---------------- helpers ----------------
__device__ __forceinline__ unsigned h2u(__half2 h) { return *reinterpret_cast<unsigned*>(&h); }
__device__ __forceinline__ __half2 u2h(unsigned u) { return *reinterpret_cast<__half2*>(&u); }

__device__ __forceinline__ void mma16(float* d, const unsigned* a, const unsigned* b) {
    asm volatile(
        "mma.sync.aligned.m16n8k16.row.col.f32.f16.f16.f32 "
        "{%0,%1,%2,%3}, {%4,%5,%6,%7}, {%8,%9}, {%0,%1,%2,%3};\n"
        : "+f"(d[0]), "+f"(d[1]), "+f"(d[2]), "+f"(d[3])
        : "r"(a[0]), "r"(a[1]), "r"(a[2]), "r"(a[3]), "r"(b[0]), "r"(b[1]));
}
__device__ __forceinline__ void cp16(void* sdst, const void* gsrc) {
    unsigned int d = (unsigned int)__cvta_generic_to_shared(sdst);
    asm volatile("cp.async.cg.shared.global [%0], [%1], 16;\n" :: "r"(d), "l"(gsrc));
}
__device__ __forceinline__ void ldsm4(unsigned* r, const void* saddr) {
    unsigned int ad = (unsigned int)__cvta_generic_to_shared(saddr);
    asm volatile("ldmatrix.sync.aligned.m8n8.x4.shared.b16 {%0,%1,%2,%3}, [%4];\n"
        : "=r"(r[0]), "=r"(r[1]), "=r"(r[2]), "=r"(r[3]) : "r"(ad));
}
__device__ __forceinline__ void ldsm4t(unsigned* r, const void* saddr) {
    unsigned int ad = (unsigned int)__cvta_generic_to_shared(saddr);
    asm volatile("ldmatrix.sync.aligned.m8n8.x4.trans.shared.b16 {%0,%1,%2,%3}, [%4];\n"
        : "=r"(r[0]), "=r"(r[1]), "=r"(r[2]), "=r"(r[3]) : "r"(ad));
}

// ---------------- fused weight fp32 -> fp16 convert ----------------
__global__ __launch_bounds__(256) void cvt_all_kernel(
    const float* __restrict__ s0, __half* __restrict__ d0, int n0,
    const float* __restrict__ s1, __half* __restrict__ d1, int n1,
    const float* __restrict__ s2, __half* __restrict__ d2, int n2,
    const float* __restrict__ s3, __half* __restrict__ d3, int n3)
{
    int i = blockIdx.x * blockDim.x + threadIdx.x;
    int stride = gridDim.x * blockDim.x;
    #define CVT_LOOP(S, D, N) \
    for (int j = i; j < N; j += stride) { \
        float4 v = reinterpret_cast<const float4*>(S)[j]; \
        __half2 lo = __floats2half2_rn(v.x, v.y); \
        __half2 hi = __floats2half2_rn(v.z, v.w); \
        reinterpret_cast<uint2*>(D)[j] = make_uint2(h2u(lo), h2u(hi)); \
    }
    CVT_LOOP(s0, d0, n0) CVT_LOOP(s1, d1, n1) CVT_LOOP(s2, d2, n2) CVT_LOOP(s3, d3, n3)
    #undef CVT_LOOP
}

// ---------------- LayerNorm (fp16 output: feeds GEMM A) ----------------
__global__ __launch_bounds__(256) void ln_kernel(
    const float* __restrict__ x, const float* __restrict__ g,
    const float* __restrict__ b, __half* __restrict__ out)
{
    int row = blockIdx.x;
    int tid = threadIdx.x;
    const float* xr = x + (size_t)row * DM;
    float4 xv = reinterpret_cast<const float4*>(xr)[tid];
    float s  = xv.x + xv.y + xv.z + xv.w;
    float sq = xv.x*xv.x + xv.y*xv.y + xv.z*xv.z + xv.w*xv.w;

    __shared__ float sh1[256], sh2[256];
    sh1[tid] = s; sh2[tid] = sq;
    __syncthreads();
    #pragma unroll
    for (int o = 128; o > 0; o >>= 1) {
        if (tid < o) { sh1[tid] += sh1[tid + o]; sh2[tid] += sh2[tid + o]; }
        __syncthreads();
    }
    float mu   = sh1[0] * (1.0f / DM);
    float var  = sh2[0] * (1.0f / DM) - mu * mu;
    float rstd = rsqrtf(var + 1e-5f);

    float4 gv = reinterpret_cast<const float4*>(g)[tid];
    float4 bv = reinterpret_cast<const float4*>(b)[tid];
    __half2 lo = __floats2half2_rn((xv.x - mu) * rstd * gv.x + bv.x,
                                   (xv.y - mu) * rstd * gv.y + bv.y);
    __half2 hi = __floats2half2_rn((xv.z - mu) * rstd * gv.z + bv.z,
                                   (xv.w - mu) * rstd * gv.w + bv.w);
    reinterpret_cast<uint2*>(out + (size_t)row * DM)[tid] = make_uint2(h2u(lo), h2u(hi));
}

// ---------------- fp16 MMA GEMM: TM x 128 block, 8 warps, BK=32 --------------
// OP = 1: float C = A*B + bias + res; OP = 2: half C = gelu(A*B + bias)
// OP = 3: QKV epilogue — L2-normalize q,k; write [H,L,64] layout
#define ASTR 40
#define BSTR 136
#define HBK  32
#define GNST 3

template<int TM, int OP>
__global__ __launch_bounds__(256) void hgemm(
    const __half* __restrict__ A, const __half* __restrict__ B,
    const float* __restrict__ bias, const float* __restrict__ res,
    void* __restrict__ Cv, __half* __restrict__ Qo, __half* __restrict__ Ko,
    __half* __restrict__ Vo, int M, int N, int K)
{
    constexpr int NWN   = (TM == 128) ? 2 : 4;
    constexpr int NT    = 16 / NWN;
    constexpr int STAGE = TM * ASTR + HBK * BSTR;

    extern __shared__ __half sh[];

    const int tid  = threadIdx.x;
    const int lane = tid & 31;
    const int warp = tid >> 5;
    const int g    = lane >> 2;
    const int tig  = lane & 3;
    const int wm   = warp / NWN;
    const int wn   = warp % NWN;
    const int m0   = blockIdx.x * TM;
    const int n0   = blockIdx.y * 128;

    const int lt = lane >> 3;
    const int li = lane & 7;
    const int arow_l = wm * 32 + (lt & 1) * 8 + li;
    const int acol_l = (lt >> 1) * 8;
    const int brow_l = (lt & 1) * 8 + li;
    const int bcol_l = wn * (NT * 8) + (lt >> 1) * 8;

    float acc[2][NT][4];
    #pragma unroll
    for (int mt = 0; mt < 2; mt++)
        #pragma unroll
        for (int nt = 0; nt < NT; nt++)
            #pragma unroll
            for (int i = 0; i < 4; i++) acc[mt][nt][i] = 0.0f;

    const int nsteps = K >> 5;

    #define LOAD_STAGE(sp, kt) do { \
        __half* As = sh + (sp) * STAGE; \
        __half* Bs = As + TM * ASTR; \
        _Pragma("unroll") \
        for (int t = 0; t < TM / 64; t++) { \
            int idx = t * 256 + tid; \
            int arw = idx >> 2, aof = (idx & 3) * 8; \
            cp16(&As[arw * ASTR + aof], A + (size_t)(m0 + arw) * K + (kt) + aof); \
        } \
        _Pragma("unroll") \
        for (int t = 0; t < 2; t++) { \
            int idx = t * 256 + tid; \
            int brw = idx >> 4, bof = (idx & 15) * 8; \
            cp16(&Bs[brw * BSTR + bof], B + (size_t)((kt) + brw) * N + n0 + bof); \
        } \
        asm volatile("cp.async.commit_group;\n"); \
    } while (0)

    #pragma unroll
    for (int s = 0; s < GNST - 1; s++) LOAD_STAGE(s, s * HBK);

    for (int it = 0; it < nsteps; it++) {
        asm volatile("cp.async.wait_group %0;\n" :: "n"(GNST - 2));
        __syncthreads();

        if (it + GNST - 1 < nsteps)
            LOAD_STAGE((it + GNST - 1) % GNST, (it + GNST - 1) * HBK);
        else
            asm volatile("cp.async.commit_group;\n");

        const __half* As = sh + (it % GNST) * STAGE;
        const __half* Bs = As + TM * ASTR;

        #pragma unroll
        for (int kb = 0; kb < HBK; kb += 16) {
            unsigned a[2][4], b[NT][2];
            ldsm4(a[0], &As[arow_l * ASTR + kb + acol_l]);
            ldsm4(a[1], &As[(arow_l + 16) * ASTR + kb + acol_l]);
            #pragma unroll
            for (int ntp = 0; ntp < NT / 2; ntp++) {
                unsigned t4[4];
                ldsm4t(t4, &Bs[(kb + brow_l) * BSTR + bcol_l + ntp * 16]);
                b[2 * ntp][0]     = t4[0]; b[2 * ntp][1]     = t4[1];
                b[2 * ntp + 1][0] = t4[2]; b[2 * ntp + 1][1] = t4[3];
            }
            #pragma unroll
            for (int mt = 0; mt < 2; mt++)
                #pragma unroll
                for (int nt = 0; nt < NT; nt++)
                    mma16(acc[mt][nt], a[mt], b[nt]);
        }
    }
    #undef LOAD_STAGE

    // ---------------- epilogue ----------------
    if (OP == 3) {
        const int grp = (n0 >> 6) + wn;
        const int cls = grp >> 4;
        const int hh  = grp & 15;
        __half* Dst = (cls == 0) ? Qo : (cls == 1) ? Ko : Vo;

        #pragma unroll
        for (int mt = 0; mt < 2; mt++) {
            const int r0 = m0 + wm * 32 + mt * 16 + g;
            const int r1 = r0 + 8;
            float v[NT][4];
            float ss0 = 0.0f, ss1 = 0.0f;
            #pragma unroll
            for (int nt = 0; nt < NT; nt++) {
                const int c = n0 + wn * (NT * 8) + nt * 8 + tig * 2;
                const float b0 = bias[c], b1 = bias[c + 1];
                v[nt][0] = acc[mt][nt][0] + b0;
                v[nt][1] = acc[mt][nt][1] + b1;
                v[nt][2] = acc[mt][nt][2] + b0;
                v[nt][3] = acc[mt][nt][3] + b1;
                ss0 += v[nt][0] * v[nt][0] + v[nt][1] * v[nt][1];
                ss1 += v[nt][2] * v[nt][2] + v[nt][3] * v[nt][3];
            }
            ss0 += __shfl_xor_sync(0xffffffffu, ss0, 1);
            ss0 += __shfl_xor_sync(0xffffffffu, ss0, 2);
            ss1 += __shfl_xor_sync(0xffffffffu, ss1, 1);
            ss1 += __shfl_xor_sync(0xffffffffu, ss1, 2);
            float sc0 = 1.0f, sc1 = 1.0f;
            if (cls == 0) {
                sc0 = 0.125f / fmaxf(sqrtf(ss0), 1e-12f);
                sc1 = 0.125f / fmaxf(sqrtf(ss1), 1e-12f);
            } else if (cls == 1) {
                sc0 = 1.0f / fmaxf(sqrtf(ss0), 1e-12f);
                sc1 = 1.0f / fmaxf(sqrtf(ss1), 1e-12f);
            }
            __half* d0p = Dst + ((size_t)hh * SEQ + r0) * HD + tig * 2;
            __half* d1p = Dst + ((size_t)hh * SEQ + r1) * HD + tig * 2;
            #pragma unroll
            for (int nt = 0; nt < NT; nt++) {
                *reinterpret_cast<unsigned*>(d0p + nt * 8) =
                    h2u(__floats2half2_rn(v[nt][0] * sc0, v[nt][1] * sc0));
                *reinterpret_cast<unsigned*>(d1p + nt * 8) =
                    h2u(__floats2half2_rn(v[nt][2] * sc1, v[nt][3] * sc1));
            }
        }
        return;
    }

    #pragma unroll
    for (int mt = 0; mt < 2; mt++) {
        const int r0 = m0 + wm * 32 + mt * 16 + g;
        const int r1 = r0 + 8;
        #pragma unroll
        for (int nt = 0; nt < NT; nt++) {
            const int c = n0 + wn * (NT * 8) + nt * 8 + tig * 2;
            const float b0 = bias[c], b1 = bias[c + 1];
            float v0 = acc[mt][nt][0] + b0;
            float v1 = acc[mt][nt][1] + b1;
            float v2 = acc[mt][nt][2] + b0;
            float v3 = acc[mt][nt][3] + b1;
            if (OP == 1) {
                float* Cf = (float*)Cv;
                const float2 ra = *reinterpret_cast<const float2*>(res + (size_t)r0 * N + c);
                const float2 rb = *reinterpret_cast<const float2*>(res + (size_t)r1 * N + c);
                *reinterpret_cast<float2*>(Cf + (size_t)r0 * N + c) = make_float2(v0 + ra.x, v1 + ra.y);
                *reinterpret_cast<float2*>(Cf + (size_t)r1 * N + c) = make_float2(v2 + rb.x, v3 + rb.y);
            } else {
                if (OP == 2) {
                    v0 = 0.5f * v0 * (1.0f + erff(v0 * 0.70710678118654752f));
                    v1 = 0.5f * v1 * (1.0f + erff(v1 * 0.70710678118654752f));
                    v2 = 0.5f * v2 * (1.0f + erff(v2 * 0.70710678118654752f));
                    v3 = 0.5f * v3 * (1.0f + erff(v3 * 0.70710678118654752f));
                }
                __half* Ch = (__half*)Cv;
                *reinterpret_cast<unsigned*>(Ch + (size_t)r0 * N + c) = h2u(__floats2half2_rn(v0, v1));
                *reinterpret_cast<unsigned*>(Ch + (size_t)r1 * N + c) = h2u(__floats2half2_rn(v2, v3));
            }
        }
    }
}

// ---------------- fp16 MMA attention, double-buffered cp.async K/V ------------
// half2 softmax (h2exp) + denominator via ones-column MMA (fp32 tensor accum).
#define QSTR 72
#define KVSTAGE (64 * QSTR)
__global__ __launch_bounds__(256) void attn_h_kernel(
    const __half* __restrict__ Q, const __half* __restrict__ Km,
    const __half* __restrict__ V, const float* __restrict__ lcc,
    __half* __restrict__ out)
{
    extern __shared__ __half apool[];
    __half* Qs = apool;
    __half* Kb = apool + 128 * QSTR;
    __half* Vb = Kb + 2 * KVSTAGE;
    __shared__ __half2 lccs[2][32];   // exp(lcc*0.05) packed per key pair

    const int h    = blockIdx.y;
    const int m0   = blockIdx.x * 128;
    const int tid  = threadIdx.x;
    const int lane = tid & 31;
    const int warp = tid >> 5;
    const int g    = lane >> 2;
    const int tig  = lane & 3;
    const int lt   = lane >> 3;
    const int li   = lane & 7;

    const int kb_n = ((lane >> 4) << 3) + li;
    const int kb_k = ((lane >> 3) & 1) * 8;

    const __half* Kg = Km + (size_t)h * SEQ * HD;
    const __half* Vg = V  + (size_t)h * SEQ * HD;

    #define LOAD_KV(sb, kt) do { \
        __half* Kd = Kb + (sb) * KVSTAGE; \
        __half* Vd = Vb + (sb) * KVSTAGE; \
        _Pragma("unroll") \
        for (int t = 0; t < 2; t++) { \
            int idx = t * 256 + tid; \
            int row = idx >> 3; \
            int off = (idx & 7) * 8; \
            cp16(&Kd[row * QSTR + off], Kg + (size_t)((kt) + row) * HD + off); \
            cp16(&Vd[row * QSTR + off], Vg + (size_t)((kt) + row) * HD + off); \
        } \
        asm volatile("cp.async.commit_group;\n"); \
        if (tid < 32) { \
            float e0 = __expf(lcc[(kt) + 2 * tid]     * 0.05f); \
            float e1 = __expf(lcc[(kt) + 2 * tid + 1] * 0.05f); \
            lccs[sb][tid] = __floats2half2_rn(e0, e1); \
        } \
    } while (0)

    LOAD_KV(0, 0);

    {
        const __half* Qg = Q + ((size_t)h * SEQ + m0) * HD;
        #pragma unroll
        for (int t = 0; t < 4; t++) {
            int idx = t * 256 + tid;
            int row = idx >> 3;
            int off = (idx & 7) * 8;
            *reinterpret_cast<uint4*>(&Qs[row * QSTR + off]) =
                *reinterpret_cast<const uint4*>(Qg + (size_t)row * HD + off);
        }
    }
    __syncthreads();

    unsigned qa[4][4];
    {
        const int qrow = warp * 16 + (lt & 1) * 8 + li;
        const int qcol = (lt >> 1) * 8;
        #pragma unroll
        for (int kc = 0; kc < 4; kc++)
            ldsm4(qa[kc], &Qs[qrow * QSTR + kc * 16 + qcol]);
    }

    float o[8][4];
    #pragma unroll
    for (int nt = 0; nt < 8; nt++)
        #pragma unroll
        for (int i = 0; i < 4; i++) o[nt][i] = 0.0f;
    float dacc[4] = {0.0f, 0.0f, 0.0f, 0.0f};
    const unsigned ones2 = h2u(__floats2half2_rn(1.0f, 1.0f));
    const unsigned b_ones[2] = {ones2, ones2};

    for (int ti = 0; ti < SEQ / 64; ti++) {
        const int buf = ti & 1;
        __syncthreads();
        if (ti + 1 < SEQ / 64) {
            LOAD_KV(buf ^ 1, (ti + 1) * 64);
        } else {
            asm volatile("cp.async.commit_group;\n");
        }
        asm volatile("cp.async.wait_group 1;\n");
        __syncthreads();

        const __half* Ks = Kb + buf * KVSTAGE;
        const __half* Vs = Vb + buf * KVSTAGE;

        float s[8][4];
        #pragma unroll
        for (int nt = 0; nt < 8; nt++)
            #pragma unroll
            for (int i = 0; i < 4; i++) s[nt][i] = 0.0f;

        #pragma unroll
        for (int kc = 0; kc < 4; kc++) {
            #pragma unroll
            for (int ng = 0; ng < 4; ng++) {
                unsigned t4[4];
                ldsm4(t4, &Ks[(ng * 16 + kb_n) * QSTR + kc * 16 + kb_k]);
                mma16(s[2 * ng],     qa[kc], t4);
                mma16(s[2 * ng + 1], qa[kc], t4 + 2);
            }
        }

        // half2 softmax numerators: p = h2exp(s) * E_c
        unsigned pa[8][2];
        #pragma unroll
        for (int nt = 0; nt < 8; nt++) {
            __half2 ec = lccs[buf][nt * 4 + tig];
            __half2 p01 = __hmul2(h2exp(__floats2half2_rn(s[nt][0], s[nt][1])), ec);
            __half2 p23 = __hmul2(h2exp(__floats2half2_rn(s[nt][2], s[nt][3])), ec);
            pa[nt][0] = h2u(p01);
            pa[nt][1] = h2u(p23);
        }

        // O += P @ V; denominator via ones-column MMA
        #pragma unroll
        for (int kc = 0; kc < 4; kc++) {
            unsigned a[4];
            a[0] = pa[2 * kc][0];
            a[1] = pa[2 * kc][1];
            a[2] = pa[2 * kc + 1][0];
            a[3] = pa[2 * kc + 1][1];
            mma16(dacc, a, b_ones);
            unsigned vb[8][2];
            #pragma unroll
            for (int ntp = 0; ntp < 4; ntp++) {
                unsigned t4[4];
                ldsm4t(t4, &Vs[(kc * 16 + (lt & 1) * 8 + li) * QSTR + (ntp * 2 + (lt >> 1)) * 8]);
                vb[2 * ntp][0]     = t4[0]; vb[2 * ntp][1]     = t4[1];
                vb[2 * ntp + 1][0] = t4[2]; vb[2 * ntp + 1][1] = t4[3];
            }
            #pragma unroll
            for (int nt = 0; nt < 8; nt++)
                mma16(o[nt], a, vb[nt]);
        }
    }
    #undef LOAD_KV

    const float inv0 = 1.0f / dacc[0];
    const float inv1 = 1.0f / dacc[2];

    const int r0 = m0 + warp * 16 + g;
    const int r1 = r0 + 8;
    #pragma unroll
    for (int nt = 0; nt < 8; nt++) {
        const int c = h * HD + nt * 8 + tig * 2;
        *reinterpret_cast<unsigned*>(out + (size_t)r0 * DM + c) =
            h2u(__floats2half2_rn(o[nt][0] * inv0, o[nt][1] * inv0));
        *reinterpret_cast<unsigned*>(out + (size_t)r1 * DM + c) =
            h2u(__floats2half2_rn(o[nt][2] * inv1, o[nt][3] * inv1));
    }
}

// ---------------- launch --------------------------------------------------------
extern "C" void kernel_launch(void* const* d_in, const int* in_sizes, int n_in,
                              void* d_out, int out_size)
{
    const float* x     = (const float*)d_in[0];
    const float* lcc   = (const float*)d_in[1];
    const float* w_qkv = (const float*)d_in[2];
    const float* b_qkv = (const float*)d_in[3];
    const float* w_out = (const float*)d_in[4];
    const float* b_out = (const float*)d_in[5];
    const float* ln1_g = (const float*)d_in[6];
    const float* ln1_b = (const float*)d_in[7];
    const float* ln2_g = (const float*)d_in[8];
    const float* ln2_b = (const float*)d_in[9];
    const float* w_ff1 = (const float*)d_in[10];
    const float* b_ff1 = (const float*)d_in[11];
    const float* w_ff2 = (const float*)d_in[12];
    const float* b_ff2 = (const float*)d_in[13];
    float* out = (float*)d_out;

    __half *normed, *q, *k, *v, *attn, *normed2, *ffh;
    __half *wqkv_h, *wout_h, *wff1_h, *wff2_h;
    float *x2;
    cudaGetSymbolAddress((void**)&normed,  g_normed);
    cudaGetSymbolAddress((void**)&q,       g_q);
    cudaGetSymbolAddress((void**)&k,       g_k);
    cudaGetSymbolAddress((void**)&v,       g_v);
    cudaGetSymbolAddress((void**)&attn,    g_attn);
    cudaGetSymbolAddress((void**)&x2,      g_x2);
    cudaGetSymbolAddress((void**)&normed2, g_normed2);
    cudaGetSymbolAddress((void**)&ffh,     g_ffh);
    cudaGetSymbolAddress((void**)&wqkv_h,  g_wqkv_h);
    cudaGetSymbolAddress((void**)&wout_h,  g_wout_h);
    cudaGetSymbolAddress((void**)&wff1_h,  g_wff1_h);
    cudaGetSymbolAddress((void**)&wff2_h,  g_wff2_h);

    const int smem128 = GNST * (128 * ASTR + HBK * BSTR) * 2;
    const int smem64  = GNST * (64 * ASTR + HBK * BSTR) * 2;
    cudaFuncSetAttribute((const void*)hgemm<128,3>, cudaFuncAttributeMaxDynamicSharedMemorySize, smem128);
    cudaFuncSetAttribute((const void*)hgemm<128,2>, cudaFuncAttributeMaxDynamicSharedMemorySize, smem128);
    cudaFuncSetAttribute((const void*)hgemm<64,1>,  cudaFuncAttributeMaxDynamicSharedMemorySize, smem64);

    const int asmem = (128 * QSTR + 4 * KVSTAGE) * 2;
    cudaFuncSetAttribute(attn_h_kernel, cudaFuncAttributeMaxDynamicSharedMemorySize, asmem);

    // 0. convert all weights to fp16 (single launch, high parallelism)
    cvt_all_kernel<<<1184, 256>>>(
        w_qkv, wqkv_h, DM * 3 * DM / 4,
        w_out, wout_h, DM * DM / 4,
        w_ff1, wff1_h, DM * DFF / 4,
        w_ff2, wff2_h, DFF * DM / 4);

    // 1. LN1 (fp16 output)
    ln_kernel<<<SEQ, 256>>>(x, ln1_g, ln1_b, normed);
    // 2. QKV projection + fused split/cosine-normalize/relayout
    hgemm<128,3><<<dim3(SEQ / 128, 3 * DM / 128), 256, smem128>>>(
        normed, wqkv_h, b_qkv, nullptr, nullptr, q, k, v, SEQ, 3 * DM, DM);
    // 3. attention (fp16 MMA, pipelined K/V)
    attn_h_kernel<<<dim3(SEQ / 128, NH), 256, asmem>>>(q, k, v, lcc, attn);
    // 4. out projection + residual (fp32 out) — 64-row tiles
    hgemm<64,1><<<dim3(SEQ / 64, DM / 128), 256, smem64>>>(
        attn, wout_h, b_out, x, x2, nullptr, nullptr, nullptr, SEQ, DM, DM);
    // 5. LN2 (fp16 output)
    ln_kernel<<<SEQ, 256>>>(x2, ln2_g, ln2_b, normed2);
    // 6. FF1 + exact GELU (fp16 output)
    hgemm<128,2><<<dim3(SEQ / 128, DFF / 128), 256, smem128>>>(
        normed2, wff1_h, b_ff1, nullptr, ffh, nullptr, nullptr, nullptr, SEQ, DFF, DM);
    // 7. FF2 + residual -> out (fp32) — 64-row tiles
    hgemm<64,1><<<dim3(SEQ / 64, DM / 128), 256, smem64>>>(
        ffh, wff2_h, b_ff2, x2, out, nullptr, nullptr, nullptr, SEQ, DM, DFF);
}